// round 5
// baseline (speedup 1.0000x reference)
#include <cuda_runtime.h>
#include <cuda_bf16.h>
#include <cstdint>
#include <math.h>

#define DIMN   256
#define BATCH  8
#define SEQ    4096
#define LRC    0.1f
#define DECAYC 0.9f
#define MTOT   (BATCH*SEQ)          // 32768
#define CH     64                   // chunk length
#define NC     (SEQ/CH)             // 64 chunks

// ---------------- scratch (device globals: allocation-free) ----------------
__device__ float g_k[BATCH*SEQ*DIMN];   // eta-scaled k
__device__ float g_v[BATCH*SEQ*DIMN];
__device__ float g_q[BATCH*SEQ*DIMN];
__device__ float g_y[BATCH*SEQ*DIMN];   // memory_out
__device__ float g_dAT[BATCH*NC*DIMN*DIMN];          // per-chunk dA^T
__device__ __nv_bfloat16 g_AsThi[BATCH*NC*DIMN*DIMN]; // prefix state^T hi
__device__ __nv_bfloat16 g_AsTlo[BATCH*NC*DIMN*DIMN]; // prefix state^T lo

__device__ __nv_bfloat16 g_xhi[MTOT*DIMN];
__device__ __nv_bfloat16 g_xlo[MTOT*DIMN];
__device__ __nv_bfloat16 g_yhi[MTOT*DIMN];
__device__ __nv_bfloat16 g_ylo[MTOT*DIMN];
__device__ __nv_bfloat16 g_whi[4*DIMN*DIMN];
__device__ __nv_bfloat16 g_wlo[4*DIMN*DIMN];

// ---------------- packed f32x2 helpers (Blackwell FFMA2) -------------------
typedef unsigned long long ull;

__device__ __forceinline__ ull pack2(float lo, float hi) {
    ull r; asm("mov.b64 %0,{%1,%2};" : "=l"(r) : "f"(lo), "f"(hi)); return r;
}
__device__ __forceinline__ void unpack2(ull p, float& lo, float& hi) {
    asm("mov.b64 {%0,%1},%2;" : "=f"(lo), "=f"(hi) : "l"(p));
}
__device__ __forceinline__ ull fma2(ull a, ull b, ull c) {
    ull d; asm("fma.rn.f32x2 %0,%1,%2,%3;" : "=l"(d) : "l"(a), "l"(b), "l"(c)); return d;
}

// ---------------- split conversion: fp32 -> bf16 hi + bf16 lo --------------
__global__ __launch_bounds__(256) void conv_split_kernel(
    const float* __restrict__ in, __nv_bfloat16* __restrict__ hi,
    __nv_bfloat16* __restrict__ lo, int n4)
{
    int i = blockIdx.x * 256 + threadIdx.x;
    if (i >= n4) return;
    float4 v = ((const float4*)in)[i];
    __nv_bfloat16 h0 = __float2bfloat16(v.x);
    __nv_bfloat16 h1 = __float2bfloat16(v.y);
    __nv_bfloat16 h2 = __float2bfloat16(v.z);
    __nv_bfloat16 h3 = __float2bfloat16(v.w);
    __nv_bfloat16 l0 = __float2bfloat16(v.x - __bfloat162float(h0));
    __nv_bfloat16 l1 = __float2bfloat16(v.y - __bfloat162float(h1));
    __nv_bfloat16 l2 = __float2bfloat16(v.z - __bfloat162float(h2));
    __nv_bfloat16 l3 = __float2bfloat16(v.w - __bfloat162float(h3));
    __nv_bfloat162* hp = (__nv_bfloat162*)hi;
    __nv_bfloat162* lp = (__nv_bfloat162*)lo;
    hp[2 * i]     = __nv_bfloat162(h0, h1);
    hp[2 * i + 1] = __nv_bfloat162(h2, h3);
    lp[2 * i]     = __nv_bfloat162(l0, l1);
    lp[2 * i + 1] = __nv_bfloat162(l2, l3);
}

// ---------------- HMMA primitives ------------------------------------------
#define ASTR 72                    // smem row stride in bf16 (144B = 9*16B)

__device__ __forceinline__ void mma16816(float* c, const uint32_t* a, const uint32_t* b) {
    asm volatile(
        "mma.sync.aligned.m16n8k16.row.col.f32.bf16.bf16.f32 "
        "{%0,%1,%2,%3}, {%4,%5,%6,%7}, {%8,%9}, {%0,%1,%2,%3};"
        : "+f"(c[0]), "+f"(c[1]), "+f"(c[2]), "+f"(c[3])
        : "r"(a[0]), "r"(a[1]), "r"(a[2]), "r"(a[3]), "r"(b[0]), "r"(b[1]));
}

// ---------------- HMMA GEMM: C = alpha*(A @ W^T + bias) --------------------
#define HG_SMEM (4 * 128 * ASTR * 2)   // 73728 bytes

__global__ __launch_bounds__(256, 1) void hmma_gemm_kernel(
    const __nv_bfloat16* __restrict__ Ahi, const __nv_bfloat16* __restrict__ Alo,
    const __nv_bfloat16* __restrict__ Whi, const __nv_bfloat16* __restrict__ Wlo,
    const float* __restrict__ bias, float* __restrict__ C, float alpha)
{
    extern __shared__ __align__(16) __nv_bfloat16 smem[];
    __nv_bfloat16* sAhi = smem;
    __nv_bfloat16* sAlo = smem + 128 * ASTR;
    __nv_bfloat16* sBhi = smem + 2 * 128 * ASTR;
    __nv_bfloat16* sBlo = smem + 3 * 128 * ASTR;

    const int tid  = threadIdx.x;
    const int wid  = tid >> 5;
    const int lane = tid & 31;
    const int gId  = lane >> 2;
    const int tig  = lane & 3;
    const int mBase = blockIdx.x * 128;
    const int nBase = blockIdx.y * 128;
    const int wm0 = (wid & 3) * 32;
    const int wn0 = (wid >> 2) * 64;

    float acc[2][8][4];
#pragma unroll
    for (int i = 0; i < 2; i++)
#pragma unroll
        for (int j = 0; j < 8; j++)
#pragma unroll
            for (int r = 0; r < 4; r++) acc[i][j][r] = 0.0f;

    const int lrow = tid >> 1;
    const int lhalf = tid & 1;

    for (int kc = 0; kc < 4; kc++) {
        __syncthreads();
        {
            const size_t ga = (size_t)(mBase + lrow) * DIMN + kc * 64 + lhalf * 32;
            const size_t gb = (size_t)(nBase + lrow) * DIMN + kc * 64 + lhalf * 32;
            const uint4* pah = (const uint4*)(Ahi + ga);
            const uint4* pal = (const uint4*)(Alo + ga);
            const uint4* pbh = (const uint4*)(Whi + gb);
            const uint4* pbl = (const uint4*)(Wlo + gb);
            __nv_bfloat16* dA = sAhi + lrow * ASTR + lhalf * 32;
            __nv_bfloat16* dAl = sAlo + lrow * ASTR + lhalf * 32;
            __nv_bfloat16* dB = sBhi + lrow * ASTR + lhalf * 32;
            __nv_bfloat16* dBl = sBlo + lrow * ASTR + lhalf * 32;
#pragma unroll
            for (int u = 0; u < 4; u++) {
                *(uint4*)(dA + u * 8)  = pah[u];
                *(uint4*)(dAl + u * 8) = pal[u];
                *(uint4*)(dB + u * 8)  = pbh[u];
                *(uint4*)(dBl + u * 8) = pbl[u];
            }
        }
        __syncthreads();

#pragma unroll
        for (int kk = 0; kk < 4; kk++) {
            const int k0 = kk * 16 + tig * 2;
            uint32_t ah[2][4], al[2][4];
#pragma unroll
            for (int i = 0; i < 2; i++) {
                const int r0 = wm0 + i * 16 + gId;
                ah[i][0] = *(const uint32_t*)(sAhi + r0 * ASTR + k0);
                ah[i][1] = *(const uint32_t*)(sAhi + (r0 + 8) * ASTR + k0);
                ah[i][2] = *(const uint32_t*)(sAhi + r0 * ASTR + k0 + 8);
                ah[i][3] = *(const uint32_t*)(sAhi + (r0 + 8) * ASTR + k0 + 8);
                al[i][0] = *(const uint32_t*)(sAlo + r0 * ASTR + k0);
                al[i][1] = *(const uint32_t*)(sAlo + (r0 + 8) * ASTR + k0);
                al[i][2] = *(const uint32_t*)(sAlo + r0 * ASTR + k0 + 8);
                al[i][3] = *(const uint32_t*)(sAlo + (r0 + 8) * ASTR + k0 + 8);
            }
            uint32_t bh[8][2], bl[8][2];
#pragma unroll
            for (int j = 0; j < 8; j++) {
                const int nr = wn0 + j * 8 + gId;
                bh[j][0] = *(const uint32_t*)(sBhi + nr * ASTR + k0);
                bh[j][1] = *(const uint32_t*)(sBhi + nr * ASTR + k0 + 8);
                bl[j][0] = *(const uint32_t*)(sBlo + nr * ASTR + k0);
                bl[j][1] = *(const uint32_t*)(sBlo + nr * ASTR + k0 + 8);
            }
#pragma unroll
            for (int i = 0; i < 2; i++)
#pragma unroll
                for (int j = 0; j < 8; j++) {
                    mma16816(acc[i][j], ah[i], bh[j]);
                    mma16816(acc[i][j], ah[i], bl[j]);
                    mma16816(acc[i][j], al[i], bh[j]);
                }
        }
    }

#pragma unroll
    for (int i = 0; i < 2; i++) {
        const int r0 = mBase + wm0 + i * 16 + gId;
#pragma unroll
        for (int j = 0; j < 8; j++) {
            const int col = nBase + wn0 + j * 8 + tig * 2;
            const float b0 = bias[col], b1 = bias[col + 1];
            float2 o0 = make_float2(alpha * (acc[i][j][0] + b0),
                                    alpha * (acc[i][j][1] + b1));
            float2 o1 = make_float2(alpha * (acc[i][j][2] + b0),
                                    alpha * (acc[i][j][3] + b1));
            *(float2*)(C + (size_t)r0 * DIMN + col)       = o0;
            *(float2*)(C + (size_t)(r0 + 8) * DIMN + col) = o1;
        }
    }
}

// ---------------- dA^T via HMMA: dAT[d2][d1] = sum_j V[j][d2]*ksc(j)*K[j][d1]
// grid: B*NC*4 (2x2 quads of 128), 256 threads, K=64 contraction.
__global__ __launch_bounds__(256) void dAT_hmma_kernel()
{
    extern __shared__ __align__(16) __nv_bfloat16 smem[];
    __nv_bfloat16* sVhi = smem;                      // A-operand: [d2][j]
    __nv_bfloat16* sVlo = smem + 128 * ASTR;
    __nv_bfloat16* sKhi = smem + 2 * 128 * ASTR;     // B-operand: [d1][j]
    __nv_bfloat16* sKlo = smem + 3 * 128 * ASTR;

    const int bid  = blockIdx.x;
    const int quad = bid & 3;
    const int bc   = bid >> 2;
    const int b = bc >> 6, c = bc & 63;
    const int t0  = c * CH;
    const int d2b = (quad & 1) * 128;   // m base
    const int d1b = (quad >> 1) * 128;  // n base

    const int tid  = threadIdx.x;
    const int wid  = tid >> 5;
    const int lane = tid & 31;
    const int gId  = lane >> 2;
    const int tig  = lane & 3;
    const int wm0 = (wid & 3) * 32;
    const int wn0 = (wid >> 2) * 64;

    // transpose-split loader: thread -> (jj = tid>>2, seg = tid&3)
    {
        const int jj  = tid >> 2;          // 0..63
        const int seg = tid & 3;           // 0..3
        const float ksc = powf(DECAYC, (float)(CH - 1 - jj));
        const size_t rowbase = ((size_t)(b * SEQ + t0 + jj)) * DIMN;
#pragma unroll
        for (int u = 0; u < 8; u++) {
            const int d = (seg + u * 4) * 4;     // 0..124 step 4 over 32 groups
            float4 vv = *(const float4*)(g_v + rowbase + d2b + d);
            float4 kv = *(const float4*)(g_k + rowbase + d1b + d);
#pragma unroll
            for (int e = 0; e < 4; e++) {
                float fv = (&vv.x)[e];
                __nv_bfloat16 h = __float2bfloat16(fv);
                sVhi[(d + e) * ASTR + jj] = h;
                sVlo[(d + e) * ASTR + jj] = __float2bfloat16(fv - __bfloat162float(h));
                float fk = (&kv.x)[e] * ksc;
                __nv_bfloat16 hk = __float2bfloat16(fk);
                sKhi[(d + e) * ASTR + jj] = hk;
                sKlo[(d + e) * ASTR + jj] = __float2bfloat16(fk - __bfloat162float(hk));
            }
        }
    }
    __syncthreads();

    float acc[2][8][4];
#pragma unroll
    for (int i = 0; i < 2; i++)
#pragma unroll
        for (int j = 0; j < 8; j++)
#pragma unroll
            for (int r = 0; r < 4; r++) acc[i][j][r] = 0.0f;

#pragma unroll
    for (int kk = 0; kk < 4; kk++) {
        const int k0 = kk * 16 + tig * 2;
        uint32_t ah[2][4], al[2][4];
#pragma unroll
        for (int i = 0; i < 2; i++) {
            const int r0 = wm0 + i * 16 + gId;
            ah[i][0] = *(const uint32_t*)(sVhi + r0 * ASTR + k0);
            ah[i][1] = *(const uint32_t*)(sVhi + (r0 + 8) * ASTR + k0);
            ah[i][2] = *(const uint32_t*)(sVhi + r0 * ASTR + k0 + 8);
            ah[i][3] = *(const uint32_t*)(sVhi + (r0 + 8) * ASTR + k0 + 8);
            al[i][0] = *(const uint32_t*)(sVlo + r0 * ASTR + k0);
            al[i][1] = *(const uint32_t*)(sVlo + (r0 + 8) * ASTR + k0);
            al[i][2] = *(const uint32_t*)(sVlo + r0 * ASTR + k0 + 8);
            al[i][3] = *(const uint32_t*)(sVlo + (r0 + 8) * ASTR + k0 + 8);
        }
        uint32_t bh[8][2], bl[8][2];
#pragma unroll
        for (int j = 0; j < 8; j++) {
            const int nr = wn0 + j * 8 + gId;
            bh[j][0] = *(const uint32_t*)(sKhi + nr * ASTR + k0);
            bh[j][1] = *(const uint32_t*)(sKhi + nr * ASTR + k0 + 8);
            bl[j][0] = *(const uint32_t*)(sKlo + nr * ASTR + k0);
            bl[j][1] = *(const uint32_t*)(sKlo + nr * ASTR + k0 + 8);
        }
#pragma unroll
        for (int i = 0; i < 2; i++)
#pragma unroll
            for (int j = 0; j < 8; j++) {
                mma16816(acc[i][j], ah[i], bh[j]);
                mma16816(acc[i][j], ah[i], bl[j]);
                mma16816(acc[i][j], al[i], bh[j]);
            }
    }

    const size_t obase = ((size_t)(b * NC + c)) * DIMN * DIMN;
#pragma unroll
    for (int i = 0; i < 2; i++) {
        const int r0 = d2b + wm0 + i * 16 + gId;
#pragma unroll
        for (int j = 0; j < 8; j++) {
            const int col = d1b + wn0 + j * 8 + tig * 2;
            *(float2*)(g_dAT + obase + (size_t)r0 * DIMN + col)
                = make_float2(acc[i][j][0], acc[i][j][1]);
            *(float2*)(g_dAT + obase + (size_t)(r0 + 8) * DIMN + col)
                = make_float2(acc[i][j][2], acc[i][j][3]);
        }
    }
}

// ---------------- state combine (transposed): AsT prefix, bf16 split -------
__global__ __launch_bounds__(256) void state_combine_kernel(
    const float* __restrict__ st_in, float* __restrict__ st_out)
{
    const int idx = blockIdx.x * 256 + threadIdx.x;
    const int b = idx >> 16;
    const int e = idx & 65535;                      // e = d2*256 + d1 (transposed)
    const int te = ((e & 255) << 8) | (e >> 8);     // original layout index
    float A = st_in[(size_t)b * 65536 + te];
    const float lc = 0.00117901845f;   // 0.9^64
    const size_t base = ((size_t)b * NC) * 65536 + e;
#pragma unroll 4
    for (int c = 0; c < NC; c++) {
        __nv_bfloat16 h = __float2bfloat16(A);
        g_AsThi[base + (size_t)c * 65536] = h;
        g_AsTlo[base + (size_t)c * 65536] = __float2bfloat16(A - __bfloat162float(h));
        A = lc * A + g_dAT[base + (size_t)c * 65536];
    }
    if (st_out) st_out[(size_t)b * 65536 + te] = A;
}

// ---------------- y_inter via HMMA: Y += lam^(i+1) Q @ A_prev --------------
// out tile 64(m=i) x 256(n=d2), K=256(d1) chunked 4x64. grid B*NC.
#define YI_SMEM ((2*64 + 2*256) * ASTR * 2)   // 92160 bytes

__global__ __launch_bounds__(256) void y_inter_hmma_kernel()
{
    extern __shared__ __align__(16) __nv_bfloat16 smem[];
    __nv_bfloat16* sQhi = smem;                       // [i][d1]
    __nv_bfloat16* sQlo = smem + 64 * ASTR;
    __nv_bfloat16* sBhi = smem + 2 * 64 * ASTR;       // [d2][d1] = AsT rows
    __nv_bfloat16* sBlo = smem + 2 * 64 * ASTR + 256 * ASTR;

    const int b  = blockIdx.x >> 6;
    const int c  = blockIdx.x & 63;
    const int t0 = c * CH;

    const int tid  = threadIdx.x;
    const int wid  = tid >> 5;
    const int lane = tid & 31;
    const int gId  = lane >> 2;
    const int tig  = lane & 3;
    const int wm0 = (wid & 1) * 32;
    const int wn0 = (wid >> 1) * 64;

    const size_t Abase = ((size_t)(b * NC + c)) * 65536;

    float acc[2][8][4];
#pragma unroll
    for (int i = 0; i < 2; i++)
#pragma unroll
        for (int j = 0; j < 8; j++)
#pragma unroll
            for (int r = 0; r < 4; r++) acc[i][j][r] = 0.0f;

    for (int kc = 0; kc < 4; kc++) {
        __syncthreads();
        // Q loader: split float q -> hi/lo. thread: row = tid>>2, seg = tid&3
        {
            const int row = tid >> 2;
            const int seg = tid & 3;
            const size_t gq = ((size_t)(b * SEQ + t0 + row)) * DIMN + kc * 64 + seg * 16;
#pragma unroll
            for (int u = 0; u < 4; u++) {
                float4 qv = *(const float4*)(g_q + gq + u * 4);
                const int k = seg * 16 + u * 4;
#pragma unroll
                for (int e = 0; e < 4; e++) {
                    float f = (&qv.x)[e];
                    __nv_bfloat16 h = __float2bfloat16(f);
                    sQhi[row * ASTR + k + e] = h;
                    sQlo[row * ASTR + k + e] = __float2bfloat16(f - __bfloat162float(h));
                }
            }
        }
        // B loader: copy AsT bf16 rows. 8 lanes per row, 8 row-waves.
        {
            const int u = tid & 7;           // uint4 index within 128B
            const int rbase = tid >> 3;      // 0..31
#pragma unroll
            for (int w = 0; w < 8; w++) {
                const int row = w * 32 + rbase;
                const size_t gofs = Abase + (size_t)row * DIMN + kc * 64 + u * 8;
                *(uint4*)(sBhi + row * ASTR + u * 8) = *(const uint4*)(g_AsThi + gofs);
                *(uint4*)(sBlo + row * ASTR + u * 8) = *(const uint4*)(g_AsTlo + gofs);
            }
        }
        __syncthreads();

#pragma unroll
        for (int kk = 0; kk < 4; kk++) {
            const int k0 = kk * 16 + tig * 2;
            uint32_t ah[2][4], al[2][4];
#pragma unroll
            for (int i = 0; i < 2; i++) {
                const int r0 = wm0 + i * 16 + gId;
                ah[i][0] = *(const uint32_t*)(sQhi + r0 * ASTR + k0);
                ah[i][1] = *(const uint32_t*)(sQhi + (r0 + 8) * ASTR + k0);
                ah[i][2] = *(const uint32_t*)(sQhi + r0 * ASTR + k0 + 8);
                ah[i][3] = *(const uint32_t*)(sQhi + (r0 + 8) * ASTR + k0 + 8);
                al[i][0] = *(const uint32_t*)(sQlo + r0 * ASTR + k0);
                al[i][1] = *(const uint32_t*)(sQlo + (r0 + 8) * ASTR + k0);
                al[i][2] = *(const uint32_t*)(sQlo + r0 * ASTR + k0 + 8);
                al[i][3] = *(const uint32_t*)(sQlo + (r0 + 8) * ASTR + k0 + 8);
            }
            uint32_t bh[8][2], bl[8][2];
#pragma unroll
            for (int j = 0; j < 8; j++) {
                const int nr = wn0 + j * 8 + gId;
                bh[j][0] = *(const uint32_t*)(sBhi + nr * ASTR + k0);
                bh[j][1] = *(const uint32_t*)(sBhi + nr * ASTR + k0 + 8);
                bl[j][0] = *(const uint32_t*)(sBlo + nr * ASTR + k0);
                bl[j][1] = *(const uint32_t*)(sBlo + nr * ASTR + k0 + 8);
            }
#pragma unroll
            for (int i = 0; i < 2; i++)
#pragma unroll
                for (int j = 0; j < 8; j++) {
                    mma16816(acc[i][j], ah[i], bh[j]);
                    mma16816(acc[i][j], ah[i], bl[j]);
                    mma16816(acc[i][j], al[i], bh[j]);
                }
        }
    }

    // epilogue: scale by lam^(i+1), accumulate into g_y
    const size_t ybase = ((size_t)(b * SEQ + t0)) * DIMN;
#pragma unroll
    for (int i = 0; i < 2; i++) {
        const int r0 = wm0 + i * 16 + gId;
        const float s0 = powf(DECAYC, (float)(r0 + 1));
        const float s1 = powf(DECAYC, (float)(r0 + 9));
#pragma unroll
        for (int j = 0; j < 8; j++) {
            const int col = wn0 + j * 8 + tig * 2;
            float* p0 = g_y + ybase + (size_t)r0 * DIMN + col;
            float* p1 = g_y + ybase + (size_t)(r0 + 8) * DIMN + col;
            float2 o0 = *(float2*)p0;
            float2 o1 = *(float2*)p1;
            o0.x += s0 * acc[i][j][0]; o0.y += s0 * acc[i][j][1];
            o1.x += s1 * acc[i][j][2]; o1.y += s1 * acc[i][j][3];
            *(float2*)p0 = o0;
            *(float2*)p1 = o1;
        }
    }
}

// ---------------- attn_local: S = mask(lam^(i-j) eta q.k), Y_intra = S@V ----
__global__ __launch_bounds__(256) void attn_local_kernel()
{
    const int b  = blockIdx.x >> 6;
    const int c  = blockIdx.x & 63;
    const int t0 = c * CH;
    const int tid = threadIdx.x;
    const int tx = tid & 15, ty = tid >> 4;
    const int i0 = ty * 4, j0 = tx * 4;

    __shared__ float Qt[64][64];
    __shared__ float Kt[64][64];
    __shared__ float Ss[64][64];

    const int lrow = tid >> 2;
    const int lc4  = (tid & 3) * 4;

    const float qsc = powf(DECAYC, (float)lrow);
    const float ksc = powf(DECAYC, -(float)lrow);
    const size_t rowbase = ((size_t)(b * SEQ + t0 + lrow)) * DIMN;

    ull s2[2][4];
#pragma unroll
    for (int r = 0; r < 2; r++)
#pragma unroll
        for (int j = 0; j < 4; j++) s2[r][j] = 0ull;

    for (int kt = 0; kt < 4; kt++) {
        float4 qv[4], kv[4];
#pragma unroll
        for (int u = 0; u < 4; u++) {
            qv[u] = *(const float4*)(g_q + rowbase + kt * 64 + lc4 + u * 16);
            kv[u] = *(const float4*)(g_k + rowbase + kt * 64 + lc4 + u * 16);
        }
        __syncthreads();
#pragma unroll
        for (int u = 0; u < 4; u++) {
            const int col = lc4 + u * 16;
            Qt[col + 0][lrow] = qv[u].x * qsc;
            Qt[col + 1][lrow] = qv[u].y * qsc;
            Qt[col + 2][lrow] = qv[u].z * qsc;
            Qt[col + 3][lrow] = qv[u].w * qsc;
            Kt[col + 0][lrow] = kv[u].x * ksc;
            Kt[col + 1][lrow] = kv[u].y * ksc;
            Kt[col + 2][lrow] = kv[u].z * ksc;
            Kt[col + 3][lrow] = kv[u].w * ksc;
        }
        __syncthreads();
#pragma unroll
        for (int kk = 0; kk < 64; kk++) {
            float4 q4 = *(const float4*)&Qt[kk][i0];
            float4 k4 = *(const float4*)&Kt[kk][j0];
            ull qp0 = pack2(q4.x, q4.y);
            ull qp1 = pack2(q4.z, q4.w);
            ull kb[4] = { pack2(k4.x, k4.x), pack2(k4.y, k4.y),
                          pack2(k4.z, k4.z), pack2(k4.w, k4.w) };
#pragma unroll
            for (int j = 0; j < 4; j++) {
                s2[0][j] = fma2(qp0, kb[j], s2[0][j]);
                s2[1][j] = fma2(qp1, kb[j], s2[1][j]);
            }
        }
    }

#pragma unroll
    for (int r = 0; r < 2; r++)
#pragma unroll
        for (int j = 0; j < 4; j++) {
            float lo, hi; unpack2(s2[r][j], lo, hi);
            const int ilo = i0 + 2 * r, ihi = ilo + 1, jc = j0 + j;
            Ss[jc][ilo] = (jc <= ilo) ? lo : 0.0f;
            Ss[jc][ihi] = (jc <= ihi) ? hi : 0.0f;
        }

    float (*Vs)[64] = Qt;
    const size_t ybase = ((size_t)(b * SEQ + t0)) * DIMN;
    for (int nt = 0; nt < 4; nt++) {
        float4 vv[4];
#pragma unroll
        for (int u = 0; u < 4; u++)
            vv[u] = *(const float4*)(g_v + rowbase + nt * 64 + lc4 + u * 16);
        __syncthreads();
#pragma unroll
        for (int u = 0; u < 4; u++)
            *(float4*)&Vs[lrow][lc4 + u * 16] = vv[u];
        __syncthreads();

        ull y2[4][2];
#pragma unroll
        for (int r = 0; r < 4; r++) { y2[r][0] = 0ull; y2[r][1] = 0ull; }
#pragma unroll
        for (int j = 0; j < 64; j++) {
            float4 s4 = *(const float4*)&Ss[j][i0];
            float4 v4 = *(const float4*)&Vs[j][tx * 4];
            ull vp0 = pack2(v4.x, v4.y), vp1 = pack2(v4.z, v4.w);
            float sr[4] = { s4.x, s4.y, s4.z, s4.w };
#pragma unroll
            for (int r = 0; r < 4; r++) {
                ull sb2 = pack2(sr[r], sr[r]);
                y2[r][0] = fma2(sb2, vp0, y2[r][0]);
                y2[r][1] = fma2(sb2, vp1, y2[r][1]);
            }
        }
#pragma unroll
        for (int r = 0; r < 4; r++) {
            float a, bb2, cc, dd;
            unpack2(y2[r][0], a, bb2);
            unpack2(y2[r][1], cc, dd);
            *(float4*)(g_y + ybase + (size_t)(i0 + r) * DIMN + nt * 64 + tx * 4)
                = make_float4(a, bb2, cc, dd);
        }
    }
}

// ---------------- launch ---------------------------------------------------
extern "C" void kernel_launch(void* const* d_in, const int* in_sizes, int n_in,
                              void* d_out, int out_size)
{
    const float* x  = (const float*)d_in[0];
    const float* st = (const float*)d_in[1];
    const float* Wk = (const float*)d_in[2];
    const float* bk = (const float*)d_in[3];
    const float* Wv = (const float*)d_in[4];
    const float* bv = (const float*)d_in[5];
    const float* Wq = (const float*)d_in[6];
    const float* bq = (const float*)d_in[7];
    const float* Wo = (const float*)d_in[8];
    const float* bo = (const float*)d_in[9];

    float* out = (float*)d_out;
    float* state_out = nullptr;
    const long long need = (long long)BATCH * SEQ * DIMN + (long long)BATCH * DIMN * DIMN;
    if ((long long)out_size >= need)
        state_out = out + (size_t)BATCH * SEQ * DIMN;

    void *p;
    cudaGetSymbolAddress(&p, g_k);   float* pk = (float*)p;
    cudaGetSymbolAddress(&p, g_v);   float* pv = (float*)p;
    cudaGetSymbolAddress(&p, g_q);   float* pq = (float*)p;
    cudaGetSymbolAddress(&p, g_y);   float* py = (float*)p;
    cudaGetSymbolAddress(&p, g_xhi); __nv_bfloat16* pxh = (__nv_bfloat16*)p;
    cudaGetSymbolAddress(&p, g_xlo); __nv_bfloat16* pxl = (__nv_bfloat16*)p;
    cudaGetSymbolAddress(&p, g_yhi); __nv_bfloat16* pyh = (__nv_bfloat16*)p;
    cudaGetSymbolAddress(&p, g_ylo); __nv_bfloat16* pyl = (__nv_bfloat16*)p;
    cudaGetSymbolAddress(&p, g_whi); __nv_bfloat16* pwh = (__nv_bfloat16*)p;
    cudaGetSymbolAddress(&p, g_wlo); __nv_bfloat16* pwl = (__nv_bfloat16*)p;

    cudaFuncSetAttribute(hmma_gemm_kernel,
                         cudaFuncAttributeMaxDynamicSharedMemorySize, HG_SMEM);
    cudaFuncSetAttribute(dAT_hmma_kernel,
                         cudaFuncAttributeMaxDynamicSharedMemorySize, HG_SMEM);
    cudaFuncSetAttribute(y_inter_hmma_kernel,
                         cudaFuncAttributeMaxDynamicSharedMemorySize, YI_SMEM);

    const int WSZ = DIMN * DIMN;          // 65536
    const int XN4 = MTOT * DIMN / 4;      // 2097152

    // split conversions
    conv_split_kernel<<<(XN4 + 255) / 256, 256>>>(x, pxh, pxl, XN4);
    conv_split_kernel<<<WSZ / 4 / 256, 256>>>(Wk, pwh + 0 * WSZ, pwl + 0 * WSZ, WSZ / 4);
    conv_split_kernel<<<WSZ / 4 / 256, 256>>>(Wv, pwh + 1 * WSZ, pwl + 1 * WSZ, WSZ / 4);
    conv_split_kernel<<<WSZ / 4 / 256, 256>>>(Wq, pwh + 2 * WSZ, pwl + 2 * WSZ, WSZ / 4);
    conv_split_kernel<<<WSZ / 4 / 256, 256>>>(Wo, pwh + 3 * WSZ, pwl + 3 * WSZ, WSZ / 4);

    dim3 ggrid(MTOT / 128, 2);

    // projections (k pre-scaled by eta = LR, including its bias)
    hmma_gemm_kernel<<<ggrid, 256, HG_SMEM>>>(pxh, pxl, pwh + 0 * WSZ, pwl + 0 * WSZ, bk, pk, LRC);
    hmma_gemm_kernel<<<ggrid, 256, HG_SMEM>>>(pxh, pxl, pwh + 1 * WSZ, pwl + 1 * WSZ, bv, pv, 1.0f);
    hmma_gemm_kernel<<<ggrid, 256, HG_SMEM>>>(pxh, pxl, pwh + 2 * WSZ, pwl + 2 * WSZ, bq, pq, 1.0f);

    // chunked scan path
    attn_local_kernel<<<BATCH * NC, 256>>>();                 // Y_intra -> g_y
    dAT_hmma_kernel<<<BATCH * NC * 4, 256, HG_SMEM>>>();      // dA^T per chunk
    state_combine_kernel<<<2048, 256>>>(st, state_out);       // prefix -> AsT bf16
    y_inter_hmma_kernel<<<BATCH * NC, 256, YI_SMEM>>>();      // g_y += lam Q@A

    // output projection
    conv_split_kernel<<<(XN4 + 255) / 256, 256>>>(py, pyh, pyl, XN4);
    hmma_gemm_kernel<<<ggrid, 256, HG_SMEM>>>(pyh, pyl, pwh + 3 * WSZ, pwl + 3 * WSZ, bo, out, 1.0f);
}

// round 6
// speedup vs baseline: 1.3043x; 1.3043x over previous
#include <cuda_runtime.h>
#include <cuda_bf16.h>
#include <cstdint>
#include <math.h>

#define DIMN   256
#define BATCH  8
#define SEQ    4096
#define LRC    0.1f
#define DECAYC 0.9f
#define MTOT   (BATCH*SEQ)          // 32768
#define CH     64                   // chunk length
#define NC     (SEQ/CH)             // 64 chunks

// ---------------- scratch (device globals: allocation-free) ----------------
__device__ float g_k[BATCH*SEQ*DIMN];   // eta-scaled k
__device__ float g_v[BATCH*SEQ*DIMN];
__device__ float g_q[BATCH*SEQ*DIMN];
__device__ float g_y[BATCH*SEQ*DIMN];   // memory_out
__device__ float g_dAT[BATCH*NC*DIMN*DIMN];           // per-chunk dA^T [d2][d1]
__device__ __nv_bfloat16 g_AsThi[BATCH*NC*DIMN*DIMN]; // prefix state^T hi
__device__ __nv_bfloat16 g_AsTlo[BATCH*NC*DIMN*DIMN]; // prefix state^T lo

__device__ __nv_bfloat16 g_xhi[MTOT*DIMN];
__device__ __nv_bfloat16 g_xlo[MTOT*DIMN];
__device__ __nv_bfloat16 g_yhi[MTOT*DIMN];
__device__ __nv_bfloat16 g_ylo[MTOT*DIMN];
__device__ __nv_bfloat16 g_qhi[MTOT*DIMN];   // emitted by Q-projection epilogue
__device__ __nv_bfloat16 g_qlo[MTOT*DIMN];
__device__ __nv_bfloat16 g_whi[4*DIMN*DIMN];
__device__ __nv_bfloat16 g_wlo[4*DIMN*DIMN];

// ---------------- packed f32x2 helpers (Blackwell FFMA2) -------------------
typedef unsigned long long ull;

__device__ __forceinline__ ull pack2(float lo, float hi) {
    ull r; asm("mov.b64 %0,{%1,%2};" : "=l"(r) : "f"(lo), "f"(hi)); return r;
}
__device__ __forceinline__ void unpack2(ull p, float& lo, float& hi) {
    asm("mov.b64 {%0,%1},%2;" : "=f"(lo), "=f"(hi) : "l"(p));
}
__device__ __forceinline__ ull fma2(ull a, ull b, ull c) {
    ull d; asm("fma.rn.f32x2 %0,%1,%2,%3;" : "=l"(d) : "l"(a), "l"(b), "l"(c)); return d;
}

// ---------------- split conversion: fp32 -> bf16 hi + bf16 lo --------------
__global__ __launch_bounds__(256) void conv_split_kernel(
    const float* __restrict__ in, __nv_bfloat16* __restrict__ hi,
    __nv_bfloat16* __restrict__ lo, int n4)
{
    int i = blockIdx.x * 256 + threadIdx.x;
    if (i >= n4) return;
    float4 v = ((const float4*)in)[i];
    __nv_bfloat16 h0 = __float2bfloat16(v.x);
    __nv_bfloat16 h1 = __float2bfloat16(v.y);
    __nv_bfloat16 h2 = __float2bfloat16(v.z);
    __nv_bfloat16 h3 = __float2bfloat16(v.w);
    __nv_bfloat16 l0 = __float2bfloat16(v.x - __bfloat162float(h0));
    __nv_bfloat16 l1 = __float2bfloat16(v.y - __bfloat162float(h1));
    __nv_bfloat16 l2 = __float2bfloat16(v.z - __bfloat162float(h2));
    __nv_bfloat16 l3 = __float2bfloat16(v.w - __bfloat162float(h3));
    __nv_bfloat162* hp = (__nv_bfloat162*)hi;
    __nv_bfloat162* lp = (__nv_bfloat162*)lo;
    hp[2 * i]     = __nv_bfloat162(h0, h1);
    hp[2 * i + 1] = __nv_bfloat162(h2, h3);
    lp[2 * i]     = __nv_bfloat162(l0, l1);
    lp[2 * i + 1] = __nv_bfloat162(l2, l3);
}

// ---------------- HMMA primitives ------------------------------------------
#define ASTR 72                    // smem row stride in bf16 (144B)

__device__ __forceinline__ void mma16816(float* c, const uint32_t* a, const uint32_t* b) {
    asm volatile(
        "mma.sync.aligned.m16n8k16.row.col.f32.bf16.bf16.f32 "
        "{%0,%1,%2,%3}, {%4,%5,%6,%7}, {%8,%9}, {%0,%1,%2,%3};"
        : "+f"(c[0]), "+f"(c[1]), "+f"(c[2]), "+f"(c[3])
        : "r"(a[0]), "r"(a[1]), "r"(a[2]), "r"(a[3]), "r"(b[0]), "r"(b[1]));
}

// ---------------- HMMA GEMM: C = alpha*(A @ W^T + bias) --------------------
// Optionally also emits bf16 hi/lo split of C (Chi/Clo non-null).
#define HG_SMEM (4 * 128 * ASTR * 2)   // 73728 bytes

__global__ __launch_bounds__(256, 1) void hmma_gemm_kernel(
    const __nv_bfloat16* __restrict__ Ahi, const __nv_bfloat16* __restrict__ Alo,
    const __nv_bfloat16* __restrict__ Whi, const __nv_bfloat16* __restrict__ Wlo,
    const float* __restrict__ bias, float* __restrict__ C, float alpha,
    __nv_bfloat16* __restrict__ Chi, __nv_bfloat16* __restrict__ Clo)
{
    extern __shared__ __align__(16) __nv_bfloat16 smem[];
    __nv_bfloat16* sAhi = smem;
    __nv_bfloat16* sAlo = smem + 128 * ASTR;
    __nv_bfloat16* sBhi = smem + 2 * 128 * ASTR;
    __nv_bfloat16* sBlo = smem + 3 * 128 * ASTR;

    const int tid  = threadIdx.x;
    const int wid  = tid >> 5;
    const int lane = tid & 31;
    const int gId  = lane >> 2;
    const int tig  = lane & 3;
    const int mBase = blockIdx.x * 128;
    const int nBase = blockIdx.y * 128;
    const int wm0 = (wid & 3) * 32;
    const int wn0 = (wid >> 2) * 64;

    float acc[2][8][4];
#pragma unroll
    for (int i = 0; i < 2; i++)
#pragma unroll
        for (int j = 0; j < 8; j++)
#pragma unroll
            for (int r = 0; r < 4; r++) acc[i][j][r] = 0.0f;

    const int lrow = tid >> 1;
    const int lhalf = tid & 1;

    for (int kc = 0; kc < 4; kc++) {
        __syncthreads();
        {
            const size_t ga = (size_t)(mBase + lrow) * DIMN + kc * 64 + lhalf * 32;
            const size_t gb = (size_t)(nBase + lrow) * DIMN + kc * 64 + lhalf * 32;
            const uint4* pah = (const uint4*)(Ahi + ga);
            const uint4* pal = (const uint4*)(Alo + ga);
            const uint4* pbh = (const uint4*)(Whi + gb);
            const uint4* pbl = (const uint4*)(Wlo + gb);
            __nv_bfloat16* dA = sAhi + lrow * ASTR + lhalf * 32;
            __nv_bfloat16* dAl = sAlo + lrow * ASTR + lhalf * 32;
            __nv_bfloat16* dB = sBhi + lrow * ASTR + lhalf * 32;
            __nv_bfloat16* dBl = sBlo + lrow * ASTR + lhalf * 32;
#pragma unroll
            for (int u = 0; u < 4; u++) {
                *(uint4*)(dA + u * 8)  = pah[u];
                *(uint4*)(dAl + u * 8) = pal[u];
                *(uint4*)(dB + u * 8)  = pbh[u];
                *(uint4*)(dBl + u * 8) = pbl[u];
            }
        }
        __syncthreads();

#pragma unroll
        for (int kk = 0; kk < 4; kk++) {
            const int k0 = kk * 16 + tig * 2;
            uint32_t ah[2][4], al[2][4];
#pragma unroll
            for (int i = 0; i < 2; i++) {
                const int r0 = wm0 + i * 16 + gId;
                ah[i][0] = *(const uint32_t*)(sAhi + r0 * ASTR + k0);
                ah[i][1] = *(const uint32_t*)(sAhi + (r0 + 8) * ASTR + k0);
                ah[i][2] = *(const uint32_t*)(sAhi + r0 * ASTR + k0 + 8);
                ah[i][3] = *(const uint32_t*)(sAhi + (r0 + 8) * ASTR + k0 + 8);
                al[i][0] = *(const uint32_t*)(sAlo + r0 * ASTR + k0);
                al[i][1] = *(const uint32_t*)(sAlo + (r0 + 8) * ASTR + k0);
                al[i][2] = *(const uint32_t*)(sAlo + r0 * ASTR + k0 + 8);
                al[i][3] = *(const uint32_t*)(sAlo + (r0 + 8) * ASTR + k0 + 8);
            }
            uint32_t bh[8][2], bl[8][2];
#pragma unroll
            for (int j = 0; j < 8; j++) {
                const int nr = wn0 + j * 8 + gId;
                bh[j][0] = *(const uint32_t*)(sBhi + nr * ASTR + k0);
                bh[j][1] = *(const uint32_t*)(sBhi + nr * ASTR + k0 + 8);
                bl[j][0] = *(const uint32_t*)(sBlo + nr * ASTR + k0);
                bl[j][1] = *(const uint32_t*)(sBlo + nr * ASTR + k0 + 8);
            }
#pragma unroll
            for (int i = 0; i < 2; i++)
#pragma unroll
                for (int j = 0; j < 8; j++) {
                    mma16816(acc[i][j], ah[i], bh[j]);
                    mma16816(acc[i][j], ah[i], bl[j]);
                    mma16816(acc[i][j], al[i], bh[j]);
                }
        }
    }

#pragma unroll
    for (int i = 0; i < 2; i++) {
        const int r0 = mBase + wm0 + i * 16 + gId;
#pragma unroll
        for (int j = 0; j < 8; j++) {
            const int col = nBase + wn0 + j * 8 + tig * 2;
            const float b0 = bias[col], b1 = bias[col + 1];
            float2 o0 = make_float2(alpha * (acc[i][j][0] + b0),
                                    alpha * (acc[i][j][1] + b1));
            float2 o1 = make_float2(alpha * (acc[i][j][2] + b0),
                                    alpha * (acc[i][j][3] + b1));
            *(float2*)(C + (size_t)r0 * DIMN + col)       = o0;
            *(float2*)(C + (size_t)(r0 + 8) * DIMN + col) = o1;
            if (Chi) {
                __nv_bfloat16 h0 = __float2bfloat16(o0.x);
                __nv_bfloat16 h1 = __float2bfloat16(o0.y);
                __nv_bfloat16 h2 = __float2bfloat16(o1.x);
                __nv_bfloat16 h3 = __float2bfloat16(o1.y);
                *(__nv_bfloat162*)(Chi + (size_t)r0 * DIMN + col)
                    = __nv_bfloat162(h0, h1);
                *(__nv_bfloat162*)(Chi + (size_t)(r0 + 8) * DIMN + col)
                    = __nv_bfloat162(h2, h3);
                *(__nv_bfloat162*)(Clo + (size_t)r0 * DIMN + col)
                    = __nv_bfloat162(__float2bfloat16(o0.x - __bfloat162float(h0)),
                                     __float2bfloat16(o0.y - __bfloat162float(h1)));
                *(__nv_bfloat162*)(Clo + (size_t)(r0 + 8) * DIMN + col)
                    = __nv_bfloat162(__float2bfloat16(o1.x - __bfloat162float(h2)),
                                     __float2bfloat16(o1.y - __bfloat162float(h3)));
            }
        }
    }
}

// ---------------- attn_local: S = mask(lam^(i-j) eta q.k), Y_intra = S@V ----
__global__ __launch_bounds__(256) void attn_local_kernel()
{
    const int b  = blockIdx.x >> 6;
    const int c  = blockIdx.x & 63;
    const int t0 = c * CH;
    const int tid = threadIdx.x;
    const int tx = tid & 15, ty = tid >> 4;
    const int i0 = ty * 4, j0 = tx * 4;

    __shared__ float Qt[64][64];
    __shared__ float Kt[64][64];
    __shared__ float Ss[64][64];

    const int lrow = tid >> 2;
    const int lc4  = (tid & 3) * 4;

    const float qsc = powf(DECAYC, (float)lrow);
    const float ksc = powf(DECAYC, -(float)lrow);
    const size_t rowbase = ((size_t)(b * SEQ + t0 + lrow)) * DIMN;

    ull s2[2][4];
#pragma unroll
    for (int r = 0; r < 2; r++)
#pragma unroll
        for (int j = 0; j < 4; j++) s2[r][j] = 0ull;

    for (int kt = 0; kt < 4; kt++) {
        float4 qv[4], kv[4];
#pragma unroll
        for (int u = 0; u < 4; u++) {
            qv[u] = *(const float4*)(g_q + rowbase + kt * 64 + lc4 + u * 16);
            kv[u] = *(const float4*)(g_k + rowbase + kt * 64 + lc4 + u * 16);
        }
        __syncthreads();
#pragma unroll
        for (int u = 0; u < 4; u++) {
            const int col = lc4 + u * 16;
            Qt[col + 0][lrow] = qv[u].x * qsc;
            Qt[col + 1][lrow] = qv[u].y * qsc;
            Qt[col + 2][lrow] = qv[u].z * qsc;
            Qt[col + 3][lrow] = qv[u].w * qsc;
            Kt[col + 0][lrow] = kv[u].x * ksc;
            Kt[col + 1][lrow] = kv[u].y * ksc;
            Kt[col + 2][lrow] = kv[u].z * ksc;
            Kt[col + 3][lrow] = kv[u].w * ksc;
        }
        __syncthreads();
#pragma unroll
        for (int kk = 0; kk < 64; kk++) {
            float4 q4 = *(const float4*)&Qt[kk][i0];
            float4 k4 = *(const float4*)&Kt[kk][j0];
            ull qp0 = pack2(q4.x, q4.y);
            ull qp1 = pack2(q4.z, q4.w);
            ull kb[4] = { pack2(k4.x, k4.x), pack2(k4.y, k4.y),
                          pack2(k4.z, k4.z), pack2(k4.w, k4.w) };
#pragma unroll
            for (int j = 0; j < 4; j++) {
                s2[0][j] = fma2(qp0, kb[j], s2[0][j]);
                s2[1][j] = fma2(qp1, kb[j], s2[1][j]);
            }
        }
    }

#pragma unroll
    for (int r = 0; r < 2; r++)
#pragma unroll
        for (int j = 0; j < 4; j++) {
            float lo, hi; unpack2(s2[r][j], lo, hi);
            const int ilo = i0 + 2 * r, ihi = ilo + 1, jc = j0 + j;
            Ss[jc][ilo] = (jc <= ilo) ? lo : 0.0f;
            Ss[jc][ihi] = (jc <= ihi) ? hi : 0.0f;
        }

    float (*Vs)[64] = Qt;
    const size_t ybase = ((size_t)(b * SEQ + t0)) * DIMN;
    for (int nt = 0; nt < 4; nt++) {
        float4 vv[4];
#pragma unroll
        for (int u = 0; u < 4; u++)
            vv[u] = *(const float4*)(g_v + rowbase + nt * 64 + lc4 + u * 16);
        __syncthreads();
#pragma unroll
        for (int u = 0; u < 4; u++)
            *(float4*)&Vs[lrow][lc4 + u * 16] = vv[u];
        __syncthreads();

        ull y2[4][2];
#pragma unroll
        for (int r = 0; r < 4; r++) { y2[r][0] = 0ull; y2[r][1] = 0ull; }
#pragma unroll
        for (int j = 0; j < 64; j++) {
            float4 s4 = *(const float4*)&Ss[j][i0];
            float4 v4 = *(const float4*)&Vs[j][tx * 4];
            ull vp0 = pack2(v4.x, v4.y), vp1 = pack2(v4.z, v4.w);
            float sr[4] = { s4.x, s4.y, s4.z, s4.w };
#pragma unroll
            for (int r = 0; r < 4; r++) {
                ull sb2 = pack2(sr[r], sr[r]);
                y2[r][0] = fma2(sb2, vp0, y2[r][0]);
                y2[r][1] = fma2(sb2, vp1, y2[r][1]);
            }
        }
#pragma unroll
        for (int r = 0; r < 4; r++) {
            float a, bb2, cc, dd;
            unpack2(y2[r][0], a, bb2);
            unpack2(y2[r][1], cc, dd);
            *(float4*)(g_y + ybase + (size_t)(i0 + r) * DIMN + nt * 64 + tx * 4)
                = make_float4(a, bb2, cc, dd);
        }
    }
}

// ---------------- dA^T (FFMA2): dAT[d2][d1] = sum_j ksc(j) V[j][d2] K[j][d1]
// grid: B*NC*4 = 2048 CTAs (2x2 tiles of 128), 256 threads
__global__ __launch_bounds__(256) void dAT_kernel()
{
    const int bid  = blockIdx.x;
    const int bc   = bid >> 2;
    const int tile = bid & 3;
    const int b = bc >> 6, c = bc & 63;
    const int t0  = c * CH;
    const int d1b = (tile & 1) * 128;
    const int d2b = (tile >> 1) * 128;

    __shared__ float Ks[32][128];
    __shared__ float Vs[32][128];

    const int tid = threadIdx.x;
    const int tx = tid & 15, ty = tid >> 4;
    const int lrow = tid >> 3;
    const int lc4  = (tid & 7) * 4;

    ull acc[8][4];
#pragma unroll
    for (int r = 0; r < 8; r++)
#pragma unroll
        for (int p = 0; p < 4; p++) acc[r][p] = 0ull;

    for (int jt = 0; jt < 2; jt++) {
        const float ksc = powf(DECAYC, (float)(CH - 1 - (jt * 32 + lrow)));
        const size_t rbase = ((size_t)(b * SEQ + t0 + jt * 32 + lrow)) * DIMN;
        float4 kv[4], vv[4];
#pragma unroll
        for (int u = 0; u < 4; u++) {
            kv[u] = *(const float4*)(g_k + rbase + d1b + lc4 + u * 32);
            vv[u] = *(const float4*)(g_v + rbase + d2b + lc4 + u * 32);
        }
        __syncthreads();
#pragma unroll
        for (int u = 0; u < 4; u++) {
            const int col = lc4 + u * 32;
            Ks[lrow][col + 0] = kv[u].x * ksc;
            Ks[lrow][col + 1] = kv[u].y * ksc;
            Ks[lrow][col + 2] = kv[u].z * ksc;
            Ks[lrow][col + 3] = kv[u].w * ksc;
            *(float4*)&Vs[lrow][col] = vv[u];
        }
        __syncthreads();
        // acc rows follow d2 (V), cols follow d1 (K) -> transposed output
#pragma unroll
        for (int j = 0; j < 32; j++) {
            float4 va = *(const float4*)&Vs[j][ty * 8];
            float4 vb = *(const float4*)&Vs[j][ty * 8 + 4];
            float4 ka = *(const float4*)&Ks[j][tx * 8];
            float4 kb = *(const float4*)&Ks[j][tx * 8 + 4];
            ull kp[4] = { pack2(ka.x, ka.y), pack2(ka.z, ka.w),
                          pack2(kb.x, kb.y), pack2(kb.z, kb.w) };
            float vr[8] = { va.x, va.y, va.z, va.w, vb.x, vb.y, vb.z, vb.w };
#pragma unroll
            for (int r = 0; r < 8; r++) {
                ull vd = pack2(vr[r], vr[r]);
#pragma unroll
                for (int p = 0; p < 4; p++)
                    acc[r][p] = fma2(vd, kp[p], acc[r][p]);
            }
        }
    }

    const size_t obase = ((size_t)(b * NC + c)) * DIMN * DIMN;
#pragma unroll
    for (int r = 0; r < 8; r++) {
        float f[8];
        unpack2(acc[r][0], f[0], f[1]);
        unpack2(acc[r][1], f[2], f[3]);
        unpack2(acc[r][2], f[4], f[5]);
        unpack2(acc[r][3], f[6], f[7]);
        float* p = g_dAT + obase + (size_t)(d2b + ty * 8 + r) * DIMN + d1b + tx * 8;
        *(float4*)(p)     = make_float4(f[0], f[1], f[2], f[3]);
        *(float4*)(p + 4) = make_float4(f[4], f[5], f[6], f[7]);
    }
}

// ---------------- state combine (transposed): AsT prefix, bf16 split -------
__global__ __launch_bounds__(256) void state_combine_kernel(
    const float* __restrict__ st_in, float* __restrict__ st_out)
{
    const int idx = blockIdx.x * 256 + threadIdx.x;
    const int b = idx >> 16;
    const int e = idx & 65535;                      // e = d2*256 + d1 (transposed)
    const int te = ((e & 255) << 8) | (e >> 8);     // original layout index
    float A = st_in[(size_t)b * 65536 + te];
    const float lc = 0.00117901845f;   // 0.9^64
    const size_t base = ((size_t)b * NC) * 65536 + e;
#pragma unroll 4
    for (int c = 0; c < NC; c++) {
        __nv_bfloat16 h = __float2bfloat16(A);
        g_AsThi[base + (size_t)c * 65536] = h;
        g_AsTlo[base + (size_t)c * 65536] = __float2bfloat16(A - __bfloat162float(h));
        A = lc * A + g_dAT[base + (size_t)c * 65536];
    }
    if (st_out) st_out[(size_t)b * 65536 + te] = A;
}

// ---------------- y_inter via HMMA: Y += lam^(i+1) Q @ A_prev --------------
// out tile 64(m=i) x 256(n=d2), K=256(d1) chunked 4x64. grid B*NC.
// A = Q split (global, vectorized load). B = AsT split rows (vectorized load).
#define YI_SMEM ((2*64 + 2*256) * ASTR * 2)   // 92160 bytes

__global__ __launch_bounds__(256) void y_inter_hmma_kernel()
{
    extern __shared__ __align__(16) __nv_bfloat16 smem[];
    __nv_bfloat16* sQhi = smem;                       // [i][d1]
    __nv_bfloat16* sQlo = smem + 64 * ASTR;
    __nv_bfloat16* sBhi = smem + 2 * 64 * ASTR;       // [d2][d1] = AsT rows
    __nv_bfloat16* sBlo = smem + 2 * 64 * ASTR + 256 * ASTR;

    const int b  = blockIdx.x >> 6;
    const int c  = blockIdx.x & 63;
    const int t0 = c * CH;

    const int tid  = threadIdx.x;
    const int wid  = tid >> 5;
    const int lane = tid & 31;
    const int gId  = lane >> 2;
    const int tig  = lane & 3;
    const int wm0 = (wid & 1) * 32;
    const int wn0 = (wid >> 1) * 64;

    const size_t Abase = ((size_t)(b * NC + c)) * 65536;

    float acc[2][8][4];
#pragma unroll
    for (int i = 0; i < 2; i++)
#pragma unroll
        for (int j = 0; j < 8; j++)
#pragma unroll
            for (int r = 0; r < 4; r++) acc[i][j][r] = 0.0f;

    for (int kc = 0; kc < 4; kc++) {
        __syncthreads();
        // Q loader (vectorized): row = tid>>2 (0..63), seg = tid&3 -> 16 bf16
        {
            const int row = tid >> 2;
            const int seg = tid & 3;
            const size_t gq = ((size_t)(b * SEQ + t0 + row)) * DIMN + kc * 64 + seg * 16;
#pragma unroll
            for (int u = 0; u < 2; u++) {
                *(uint4*)(sQhi + row * ASTR + seg * 16 + u * 8)
                    = *(const uint4*)(g_qhi + gq + u * 8);
                *(uint4*)(sQlo + row * ASTR + seg * 16 + u * 8)
                    = *(const uint4*)(g_qlo + gq + u * 8);
            }
        }
        // B loader (vectorized): 256 rows, 8 lanes/row x 16B, 8 row-waves
        {
            const int u = tid & 7;
            const int rbase = tid >> 3;
#pragma unroll
            for (int w = 0; w < 8; w++) {
                const int row = w * 32 + rbase;
                const size_t gofs = Abase + (size_t)row * DIMN + kc * 64 + u * 8;
                *(uint4*)(sBhi + row * ASTR + u * 8) = *(const uint4*)(g_AsThi + gofs);
                *(uint4*)(sBlo + row * ASTR + u * 8) = *(const uint4*)(g_AsTlo + gofs);
            }
        }
        __syncthreads();

#pragma unroll
        for (int kk = 0; kk < 4; kk++) {
            const int k0 = kk * 16 + tig * 2;
            uint32_t ah[2][4], al[2][4];
#pragma unroll
            for (int i = 0; i < 2; i++) {
                const int r0 = wm0 + i * 16 + gId;
                ah[i][0] = *(const uint32_t*)(sQhi + r0 * ASTR + k0);
                ah[i][1] = *(const uint32_t*)(sQhi + (r0 + 8) * ASTR + k0);
                ah[i][2] = *(const uint32_t*)(sQhi + r0 * ASTR + k0 + 8);
                ah[i][3] = *(const uint32_t*)(sQhi + (r0 + 8) * ASTR + k0 + 8);
                al[i][0] = *(const uint32_t*)(sQlo + r0 * ASTR + k0);
                al[i][1] = *(const uint32_t*)(sQlo + (r0 + 8) * ASTR + k0);
                al[i][2] = *(const uint32_t*)(sQlo + r0 * ASTR + k0 + 8);
                al[i][3] = *(const uint32_t*)(sQlo + (r0 + 8) * ASTR + k0 + 8);
            }
            uint32_t bh[8][2], bl[8][2];
#pragma unroll
            for (int j = 0; j < 8; j++) {
                const int nr = wn0 + j * 8 + gId;
                bh[j][0] = *(const uint32_t*)(sBhi + nr * ASTR + k0);
                bh[j][1] = *(const uint32_t*)(sBhi + nr * ASTR + k0 + 8);
                bl[j][0] = *(const uint32_t*)(sBlo + nr * ASTR + k0);
                bl[j][1] = *(const uint32_t*)(sBlo + nr * ASTR + k0 + 8);
            }
#pragma unroll
            for (int i = 0; i < 2; i++)
#pragma unroll
                for (int j = 0; j < 8; j++) {
                    mma16816(acc[i][j], ah[i], bh[j]);
                    mma16816(acc[i][j], ah[i], bl[j]);
                    mma16816(acc[i][j], al[i], bh[j]);
                }
        }
    }

    // epilogue: scale by lam^(i+1), accumulate into g_y
    const size_t ybase = ((size_t)(b * SEQ + t0)) * DIMN;
#pragma unroll
    for (int i = 0; i < 2; i++) {
        const int r0 = wm0 + i * 16 + gId;
        const float s0 = powf(DECAYC, (float)(r0 + 1));
        const float s1 = powf(DECAYC, (float)(r0 + 9));
#pragma unroll
        for (int j = 0; j < 8; j++) {
            const int col = wn0 + j * 8 + tig * 2;
            float* p0 = g_y + ybase + (size_t)r0 * DIMN + col;
            float* p1 = g_y + ybase + (size_t)(r0 + 8) * DIMN + col;
            float2 o0 = *(float2*)p0;
            float2 o1 = *(float2*)p1;
            o0.x += s0 * acc[i][j][0]; o0.y += s0 * acc[i][j][1];
            o1.x += s1 * acc[i][j][2]; o1.y += s1 * acc[i][j][3];
            *(float2*)p0 = o0;
            *(float2*)p1 = o1;
        }
    }
}

// ---------------- launch ---------------------------------------------------
extern "C" void kernel_launch(void* const* d_in, const int* in_sizes, int n_in,
                              void* d_out, int out_size)
{
    const float* x  = (const float*)d_in[0];
    const float* st = (const float*)d_in[1];
    const float* Wk = (const float*)d_in[2];
    const float* bk = (const float*)d_in[3];
    const float* Wv = (const float*)d_in[4];
    const float* bv = (const float*)d_in[5];
    const float* Wq = (const float*)d_in[6];
    const float* bq = (const float*)d_in[7];
    const float* Wo = (const float*)d_in[8];
    const float* bo = (const float*)d_in[9];

    float* out = (float*)d_out;
    float* state_out = nullptr;
    const long long need = (long long)BATCH * SEQ * DIMN + (long long)BATCH * DIMN * DIMN;
    if ((long long)out_size >= need)
        state_out = out + (size_t)BATCH * SEQ * DIMN;

    void *p;
    cudaGetSymbolAddress(&p, g_k);   float* pk = (float*)p;
    cudaGetSymbolAddress(&p, g_v);   float* pv = (float*)p;
    cudaGetSymbolAddress(&p, g_q);   float* pq = (float*)p;
    cudaGetSymbolAddress(&p, g_y);   float* py = (float*)p;
    cudaGetSymbolAddress(&p, g_xhi); __nv_bfloat16* pxh = (__nv_bfloat16*)p;
    cudaGetSymbolAddress(&p, g_xlo); __nv_bfloat16* pxl = (__nv_bfloat16*)p;
    cudaGetSymbolAddress(&p, g_yhi); __nv_bfloat16* pyh = (__nv_bfloat16*)p;
    cudaGetSymbolAddress(&p, g_ylo); __nv_bfloat16* pyl = (__nv_bfloat16*)p;
    cudaGetSymbolAddress(&p, g_qhi); __nv_bfloat16* pqh = (__nv_bfloat16*)p;
    cudaGetSymbolAddress(&p, g_qlo); __nv_bfloat16* pql = (__nv_bfloat16*)p;
    cudaGetSymbolAddress(&p, g_whi); __nv_bfloat16* pwh = (__nv_bfloat16*)p;
    cudaGetSymbolAddress(&p, g_wlo); __nv_bfloat16* pwl = (__nv_bfloat16*)p;

    cudaFuncSetAttribute(hmma_gemm_kernel,
                         cudaFuncAttributeMaxDynamicSharedMemorySize, HG_SMEM);
    cudaFuncSetAttribute(y_inter_hmma_kernel,
                         cudaFuncAttributeMaxDynamicSharedMemorySize, YI_SMEM);

    const int WSZ = DIMN * DIMN;          // 65536
    const int XN4 = MTOT * DIMN / 4;      // 2097152

    // split conversions
    conv_split_kernel<<<(XN4 + 255) / 256, 256>>>(x, pxh, pxl, XN4);
    conv_split_kernel<<<WSZ / 4 / 256, 256>>>(Wk, pwh + 0 * WSZ, pwl + 0 * WSZ, WSZ / 4);
    conv_split_kernel<<<WSZ / 4 / 256, 256>>>(Wv, pwh + 1 * WSZ, pwl + 1 * WSZ, WSZ / 4);
    conv_split_kernel<<<WSZ / 4 / 256, 256>>>(Wq, pwh + 2 * WSZ, pwl + 2 * WSZ, WSZ / 4);
    conv_split_kernel<<<WSZ / 4 / 256, 256>>>(Wo, pwh + 3 * WSZ, pwl + 3 * WSZ, WSZ / 4);

    dim3 ggrid(MTOT / 128, 2);

    // projections (k pre-scaled by eta = LR; q also emits bf16 split)
    hmma_gemm_kernel<<<ggrid, 256, HG_SMEM>>>(pxh, pxl, pwh + 0 * WSZ, pwl + 0 * WSZ,
                                              bk, pk, LRC, nullptr, nullptr);
    hmma_gemm_kernel<<<ggrid, 256, HG_SMEM>>>(pxh, pxl, pwh + 1 * WSZ, pwl + 1 * WSZ,
                                              bv, pv, 1.0f, nullptr, nullptr);
    hmma_gemm_kernel<<<ggrid, 256, HG_SMEM>>>(pxh, pxl, pwh + 2 * WSZ, pwl + 2 * WSZ,
                                              bq, pq, 1.0f, pqh, pql);

    // chunked scan path
    attn_local_kernel<<<BATCH * NC, 256>>>();                 // Y_intra -> g_y
    dAT_kernel<<<BATCH * NC * 4, 256>>>();                    // dA^T per chunk
    state_combine_kernel<<<2048, 256>>>(st, state_out);       // prefix -> AsT bf16
    y_inter_hmma_kernel<<<BATCH * NC, 256, YI_SMEM>>>();      // g_y += lam Q@A

    // output projection
    conv_split_kernel<<<(XN4 + 255) / 256, 256>>>(py, pyh, pyl, XN4);
    hmma_gemm_kernel<<<ggrid, 256, HG_SMEM>>>(pyh, pyl, pwh + 3 * WSZ, pwl + 3 * WSZ,
                                              bo, out, 1.0f, nullptr, nullptr);
}

// round 9
// speedup vs baseline: 1.3973x; 1.0713x over previous
#include <cuda_runtime.h>
#include <cuda_bf16.h>
#include <cstdint>
#include <math.h>

#define DIMN   256
#define BATCH  8
#define SEQ    4096
#define LRC    0.1f
#define DECAYC 0.9f
#define MTOT   (BATCH*SEQ)          // 32768
#define CH     64                   // chunk length
#define NC     (SEQ/CH)             // 64 chunks

// ---------------- scratch (device globals: allocation-free) ----------------
__device__ float g_k[BATCH*SEQ*DIMN];   // eta-scaled k
__device__ float g_v[BATCH*SEQ*DIMN];
__device__ float g_q[BATCH*SEQ*DIMN];
__device__ float g_y[BATCH*SEQ*DIMN];   // memory_out
__device__ float g_dAT[BATCH*NC*DIMN*DIMN];           // per-chunk dA^T [d2][d1]
__device__ __nv_bfloat16 g_AsThi[BATCH*NC*DIMN*DIMN]; // prefix state^T hi
__device__ __nv_bfloat16 g_AsTlo[BATCH*NC*DIMN*DIMN]; // prefix state^T lo

__device__ __nv_bfloat16 g_xhi[MTOT*DIMN];
__device__ __nv_bfloat16 g_xlo[MTOT*DIMN];
__device__ __nv_bfloat16 g_yhi[MTOT*DIMN];   // emitted by y_inter epilogue
__device__ __nv_bfloat16 g_ylo[MTOT*DIMN];
__device__ __nv_bfloat16 g_qhi[MTOT*DIMN];   // emitted by Q-projection epilogue
__device__ __nv_bfloat16 g_qlo[MTOT*DIMN];
__device__ __nv_bfloat16 g_khi[MTOT*DIMN];   // emitted by K-projection epilogue
__device__ __nv_bfloat16 g_klo[MTOT*DIMN];
__device__ __nv_bfloat16 g_whi[4*DIMN*DIMN];
__device__ __nv_bfloat16 g_wlo[4*DIMN*DIMN];

// ---------------- packed f32x2 helpers (Blackwell FFMA2) -------------------
typedef unsigned long long ull;

__device__ __forceinline__ ull pack2(float lo, float hi) {
    ull r; asm("mov.b64 %0,{%1,%2};" : "=l"(r) : "f"(lo), "f"(hi)); return r;
}
__device__ __forceinline__ void unpack2(ull p, float& lo, float& hi) {
    asm("mov.b64 {%0,%1},%2;" : "=f"(lo), "=f"(hi) : "l"(p));
}
__device__ __forceinline__ ull fma2(ull a, ull b, ull c) {
    ull d; asm("fma.rn.f32x2 %0,%1,%2,%3;" : "=l"(d) : "l"(a), "l"(b), "l"(c)); return d;
}

// ---------------- split conversion: fp32 -> bf16 hi + bf16 lo --------------
__global__ __launch_bounds__(256) void conv_split_kernel(
    const float* __restrict__ in, __nv_bfloat16* __restrict__ hi,
    __nv_bfloat16* __restrict__ lo, int n4)
{
    int i = blockIdx.x * 256 + threadIdx.x;
    if (i >= n4) return;
    float4 v = ((const float4*)in)[i];
    __nv_bfloat16 h0 = __float2bfloat16(v.x);
    __nv_bfloat16 h1 = __float2bfloat16(v.y);
    __nv_bfloat16 h2 = __float2bfloat16(v.z);
    __nv_bfloat16 h3 = __float2bfloat16(v.w);
    __nv_bfloat16 l0 = __float2bfloat16(v.x - __bfloat162float(h0));
    __nv_bfloat16 l1 = __float2bfloat16(v.y - __bfloat162float(h1));
    __nv_bfloat16 l2 = __float2bfloat16(v.z - __bfloat162float(h2));
    __nv_bfloat16 l3 = __float2bfloat16(v.w - __bfloat162float(h3));
    __nv_bfloat162* hp = (__nv_bfloat162*)hi;
    __nv_bfloat162* lp = (__nv_bfloat162*)lo;
    hp[2 * i]     = __nv_bfloat162(h0, h1);
    hp[2 * i + 1] = __nv_bfloat162(h2, h3);
    lp[2 * i]     = __nv_bfloat162(l0, l1);
    lp[2 * i + 1] = __nv_bfloat162(l2, l3);
}

// ---------------- HMMA primitives ------------------------------------------
#define ASTR 72                    // smem row stride in bf16 (144B)

__device__ __forceinline__ void mma16816(float* c, const uint32_t* a, const uint32_t* b) {
    asm volatile(
        "mma.sync.aligned.m16n8k16.row.col.f32.bf16.bf16.f32 "
        "{%0,%1,%2,%3}, {%4,%5,%6,%7}, {%8,%9}, {%0,%1,%2,%3};"
        : "+f"(c[0]), "+f"(c[1]), "+f"(c[2]), "+f"(c[3])
        : "r"(a[0]), "r"(a[1]), "r"(a[2]), "r"(a[3]), "r"(b[0]), "r"(b[1]));
}

// ---------------- HMMA GEMM: C = alpha*(A @ W^T + bias) --------------------
// Optionally also emits bf16 hi/lo split of C (Chi/Clo non-null).
#define HG_SMEM (4 * 128 * ASTR * 2)   // 73728 bytes

__global__ __launch_bounds__(256, 2) void hmma_gemm_kernel(
    const __nv_bfloat16* __restrict__ Ahi, const __nv_bfloat16* __restrict__ Alo,
    const __nv_bfloat16* __restrict__ Whi, const __nv_bfloat16* __restrict__ Wlo,
    const float* __restrict__ bias, float* __restrict__ C, float alpha,
    __nv_bfloat16* __restrict__ Chi, __nv_bfloat16* __restrict__ Clo)
{
    extern __shared__ __align__(16) __nv_bfloat16 smem[];
    __nv_bfloat16* sAhi = smem;
    __nv_bfloat16* sAlo = smem + 128 * ASTR;
    __nv_bfloat16* sBhi = smem + 2 * 128 * ASTR;
    __nv_bfloat16* sBlo = smem + 3 * 128 * ASTR;

    const int tid  = threadIdx.x;
    const int wid  = tid >> 5;
    const int lane = tid & 31;
    const int gId  = lane >> 2;
    const int tig  = lane & 3;
    const int mBase = blockIdx.x * 128;
    const int nBase = blockIdx.y * 128;
    const int wm0 = (wid & 3) * 32;
    const int wn0 = (wid >> 2) * 64;

    float acc[2][8][4];
#pragma unroll
    for (int i = 0; i < 2; i++)
#pragma unroll
        for (int j = 0; j < 8; j++)
#pragma unroll
            for (int r = 0; r < 4; r++) acc[i][j][r] = 0.0f;

    const int lrow = tid >> 1;
    const int lhalf = tid & 1;

    for (int kc = 0; kc < 4; kc++) {
        __syncthreads();
        {
            const size_t ga = (size_t)(mBase + lrow) * DIMN + kc * 64 + lhalf * 32;
            const size_t gb = (size_t)(nBase + lrow) * DIMN + kc * 64 + lhalf * 32;
            const uint4* pah = (const uint4*)(Ahi + ga);
            const uint4* pal = (const uint4*)(Alo + ga);
            const uint4* pbh = (const uint4*)(Whi + gb);
            const uint4* pbl = (const uint4*)(Wlo + gb);
            __nv_bfloat16* dA = sAhi + lrow * ASTR + lhalf * 32;
            __nv_bfloat16* dAl = sAlo + lrow * ASTR + lhalf * 32;
            __nv_bfloat16* dB = sBhi + lrow * ASTR + lhalf * 32;
            __nv_bfloat16* dBl = sBlo + lrow * ASTR + lhalf * 32;
#pragma unroll
            for (int u = 0; u < 4; u++) {
                *(uint4*)(dA + u * 8)  = pah[u];
                *(uint4*)(dAl + u * 8) = pal[u];
                *(uint4*)(dB + u * 8)  = pbh[u];
                *(uint4*)(dBl + u * 8) = pbl[u];
            }
        }
        __syncthreads();

#pragma unroll
        for (int kk = 0; kk < 4; kk++) {
            const int k0 = kk * 16 + tig * 2;
            uint32_t ah[2][4], al[2][4];
#pragma unroll
            for (int i = 0; i < 2; i++) {
                const int r0 = wm0 + i * 16 + gId;
                ah[i][0] = *(const uint32_t*)(sAhi + r0 * ASTR + k0);
                ah[i][1] = *(const uint32_t*)(sAhi + (r0 + 8) * ASTR + k0);
                ah[i][2] = *(const uint32_t*)(sAhi + r0 * ASTR + k0 + 8);
                ah[i][3] = *(const uint32_t*)(sAhi + (r0 + 8) * ASTR + k0 + 8);
                al[i][0] = *(const uint32_t*)(sAlo + r0 * ASTR + k0);
                al[i][1] = *(const uint32_t*)(sAlo + (r0 + 8) * ASTR + k0);
                al[i][2] = *(const uint32_t*)(sAlo + r0 * ASTR + k0 + 8);
                al[i][3] = *(const uint32_t*)(sAlo + (r0 + 8) * ASTR + k0 + 8);
            }
#pragma unroll
            for (int j = 0; j < 8; j++) {          // B frags loaded in-loop (reg pressure)
                const int nr = wn0 + j * 8 + gId;
                uint32_t bh[2], bl[2];
                bh[0] = *(const uint32_t*)(sBhi + nr * ASTR + k0);
                bh[1] = *(const uint32_t*)(sBhi + nr * ASTR + k0 + 8);
                bl[0] = *(const uint32_t*)(sBlo + nr * ASTR + k0);
                bl[1] = *(const uint32_t*)(sBlo + nr * ASTR + k0 + 8);
                mma16816(acc[0][j], ah[0], bh);
                mma16816(acc[0][j], ah[0], bl);
                mma16816(acc[0][j], al[0], bh);
                mma16816(acc[1][j], ah[1], bh);
                mma16816(acc[1][j], ah[1], bl);
                mma16816(acc[1][j], al[1], bh);
            }
        }
    }

#pragma unroll
    for (int i = 0; i < 2; i++) {
        const int r0 = mBase + wm0 + i * 16 + gId;
#pragma unroll
        for (int j = 0; j < 8; j++) {
            const int col = nBase + wn0 + j * 8 + tig * 2;
            const float b0 = bias[col], b1 = bias[col + 1];
            float2 o0 = make_float2(alpha * (acc[i][j][0] + b0),
                                    alpha * (acc[i][j][1] + b1));
            float2 o1 = make_float2(alpha * (acc[i][j][2] + b0),
                                    alpha * (acc[i][j][3] + b1));
            *(float2*)(C + (size_t)r0 * DIMN + col)       = o0;
            *(float2*)(C + (size_t)(r0 + 8) * DIMN + col) = o1;
            if (Chi) {
                __nv_bfloat16 h0 = __float2bfloat16(o0.x);
                __nv_bfloat16 h1 = __float2bfloat16(o0.y);
                __nv_bfloat16 h2 = __float2bfloat16(o1.x);
                __nv_bfloat16 h3 = __float2bfloat16(o1.y);
                *(__nv_bfloat162*)(Chi + (size_t)r0 * DIMN + col)
                    = __nv_bfloat162(h0, h1);
                *(__nv_bfloat162*)(Chi + (size_t)(r0 + 8) * DIMN + col)
                    = __nv_bfloat162(h2, h3);
                *(__nv_bfloat162*)(Clo + (size_t)r0 * DIMN + col)
                    = __nv_bfloat162(__float2bfloat16(o0.x - __bfloat162float(h0)),
                                     __float2bfloat16(o0.y - __bfloat162float(h1)));
                *(__nv_bfloat162*)(Clo + (size_t)(r0 + 8) * DIMN + col)
                    = __nv_bfloat162(__float2bfloat16(o1.x - __bfloat162float(h2)),
                                     __float2bfloat16(o1.y - __bfloat162float(h3)));
            }
        }
    }
}

// ---------------- attn_local: phase1 HMMA (S=QK^T), phase2 FFMA2 (S@V) -----
// grid B*NC. smem: q/k splits (bf16) + Ss fp32 [64][68] + Vs fp32 [64][64].
#define AL_SSOFF (4 * 64 * ASTR)               // bf16 elems before float region
#define AL_SMEM  (4*64*ASTR*2 + 64*68*4 + 64*64*4)   // 70656 bytes

__global__ __launch_bounds__(256, 2) void attn_local_kernel()
{
    extern __shared__ __align__(16) __nv_bfloat16 smem[];
    __nv_bfloat16* sQhi = smem;
    __nv_bfloat16* sQlo = smem + 64 * ASTR;
    __nv_bfloat16* sKhi = smem + 2 * 64 * ASTR;
    __nv_bfloat16* sKlo = smem + 3 * 64 * ASTR;
    float* Ss = (float*)(smem + AL_SSOFF);     // [64][68] layout [j][i]
    float* Vs = Ss + 64 * 68;                  // [64][64] layout [j][d]

    const int b  = blockIdx.x >> 6;
    const int c  = blockIdx.x & 63;
    const int t0 = c * CH;
    const int tid  = threadIdx.x;
    const int wid  = tid >> 5;
    const int lane = tid & 31;
    const int gId  = lane >> 2;
    const int tig  = lane & 3;
    const int wm0 = (wid & 1) * 32;            // i
    const int wn0 = (wid >> 1) * 16;           // j

    // ---- phase 1: S_raw = Q K^T (bf16x3) ----
    float acc[2][2][4];
#pragma unroll
    for (int i = 0; i < 2; i++)
#pragma unroll
        for (int j = 0; j < 2; j++)
#pragma unroll
            for (int r = 0; r < 4; r++) acc[i][j][r] = 0.0f;

    const int lrw = tid >> 2;                  // 0..63
    const int seg = tid & 3;

    for (int kc = 0; kc < 4; kc++) {
        __syncthreads();
        {
            const size_t g = ((size_t)(b * SEQ + t0 + lrw)) * DIMN + kc * 64 + seg * 16;
#pragma unroll
            for (int u = 0; u < 2; u++) {
                *(uint4*)(sQhi + lrw * ASTR + seg * 16 + u * 8) = *(const uint4*)(g_qhi + g + u * 8);
                *(uint4*)(sQlo + lrw * ASTR + seg * 16 + u * 8) = *(const uint4*)(g_qlo + g + u * 8);
                *(uint4*)(sKhi + lrw * ASTR + seg * 16 + u * 8) = *(const uint4*)(g_khi + g + u * 8);
                *(uint4*)(sKlo + lrw * ASTR + seg * 16 + u * 8) = *(const uint4*)(g_klo + g + u * 8);
            }
        }
        __syncthreads();

#pragma unroll
        for (int kk = 0; kk < 4; kk++) {
            const int k0 = kk * 16 + tig * 2;
            uint32_t ah[2][4], al[2][4];
#pragma unroll
            for (int i = 0; i < 2; i++) {
                const int r0 = wm0 + i * 16 + gId;
                ah[i][0] = *(const uint32_t*)(sQhi + r0 * ASTR + k0);
                ah[i][1] = *(const uint32_t*)(sQhi + (r0 + 8) * ASTR + k0);
                ah[i][2] = *(const uint32_t*)(sQhi + r0 * ASTR + k0 + 8);
                ah[i][3] = *(const uint32_t*)(sQhi + (r0 + 8) * ASTR + k0 + 8);
                al[i][0] = *(const uint32_t*)(sQlo + r0 * ASTR + k0);
                al[i][1] = *(const uint32_t*)(sQlo + (r0 + 8) * ASTR + k0);
                al[i][2] = *(const uint32_t*)(sQlo + r0 * ASTR + k0 + 8);
                al[i][3] = *(const uint32_t*)(sQlo + (r0 + 8) * ASTR + k0 + 8);
            }
#pragma unroll
            for (int jt = 0; jt < 2; jt++) {
                const int nr = wn0 + jt * 8 + gId;
                uint32_t bh[2], bl[2];
                bh[0] = *(const uint32_t*)(sKhi + nr * ASTR + k0);
                bh[1] = *(const uint32_t*)(sKhi + nr * ASTR + k0 + 8);
                bl[0] = *(const uint32_t*)(sKlo + nr * ASTR + k0);
                bl[1] = *(const uint32_t*)(sKlo + nr * ASTR + k0 + 8);
                mma16816(acc[0][jt], ah[0], bh);
                mma16816(acc[0][jt], ah[0], bl);
                mma16816(acc[0][jt], al[0], bh);
                mma16816(acc[1][jt], ah[1], bh);
                mma16816(acc[1][jt], ah[1], bl);
                mma16816(acc[1][jt], al[1], bh);
            }
        }
    }

    // mask + lam^(i-j) scale + write Ss[j][i]
    {
        float li[2][2], lj[2][2];
#pragma unroll
        for (int it = 0; it < 2; it++) {
            const int i1 = wm0 + it * 16 + gId;
            li[it][0] = powf(DECAYC, (float)i1);
            li[it][1] = powf(DECAYC, (float)(i1 + 8));
        }
#pragma unroll
        for (int jt = 0; jt < 2; jt++) {
            const int j1 = wn0 + jt * 8 + tig * 2;
            lj[jt][0] = powf(DECAYC, -(float)j1);
            lj[jt][1] = powf(DECAYC, -(float)(j1 + 1));
        }
#pragma unroll
        for (int it = 0; it < 2; it++) {
            const int i1 = wm0 + it * 16 + gId;
            const int i2 = i1 + 8;
#pragma unroll
            for (int jt = 0; jt < 2; jt++) {
                const int j1 = wn0 + jt * 8 + tig * 2;
                const int j2 = j1 + 1;
                Ss[j1 * 68 + i1] = (j1 <= i1) ? acc[it][jt][0] * li[it][0] * lj[jt][0] : 0.0f;
                Ss[j2 * 68 + i1] = (j2 <= i1) ? acc[it][jt][1] * li[it][0] * lj[jt][1] : 0.0f;
                Ss[j1 * 68 + i2] = (j1 <= i2) ? acc[it][jt][2] * li[it][1] * lj[jt][0] : 0.0f;
                Ss[j2 * 68 + i2] = (j2 <= i2) ? acc[it][jt][3] * li[it][1] * lj[jt][1] : 0.0f;
            }
        }
    }

    // ---- phase 2: Y_intra = S @ V (FFMA2) ----
    const int tx = tid & 15, ty = tid >> 4;
    const int i0 = ty * 4;
    const int lc4 = (tid & 3) * 4;
    const size_t rowbase = ((size_t)(b * SEQ + t0 + lrw)) * DIMN;
    const size_t ybase   = ((size_t)(b * SEQ + t0)) * DIMN;

    for (int nt = 0; nt < 4; nt++) {
        float4 vv[4];
#pragma unroll
        for (int u = 0; u < 4; u++)
            vv[u] = *(const float4*)(g_v + rowbase + nt * 64 + lc4 + u * 16);
        __syncthreads();
#pragma unroll
        for (int u = 0; u < 4; u++)
            *(float4*)&Vs[lrw * 64 + lc4 + u * 16] = vv[u];
        __syncthreads();

        ull y2[4][2];
#pragma unroll
        for (int r = 0; r < 4; r++) { y2[r][0] = 0ull; y2[r][1] = 0ull; }
#pragma unroll
        for (int j = 0; j < 64; j++) {
            float4 s4 = *(const float4*)&Ss[j * 68 + i0];
            float4 v4 = *(const float4*)&Vs[j * 64 + tx * 4];
            ull vp0 = pack2(v4.x, v4.y), vp1 = pack2(v4.z, v4.w);
            float sr[4] = { s4.x, s4.y, s4.z, s4.w };
#pragma unroll
            for (int r = 0; r < 4; r++) {
                ull sb2 = pack2(sr[r], sr[r]);
                y2[r][0] = fma2(sb2, vp0, y2[r][0]);
                y2[r][1] = fma2(sb2, vp1, y2[r][1]);
            }
        }
#pragma unroll
        for (int r = 0; r < 4; r++) {
            float a, bb2, cc, dd;
            unpack2(y2[r][0], a, bb2);
            unpack2(y2[r][1], cc, dd);
            *(float4*)(g_y + ybase + (size_t)(i0 + r) * DIMN + nt * 64 + tx * 4)
                = make_float4(a, bb2, cc, dd);
        }
    }
}

// ---------------- dA^T (FFMA2): dAT[d2][d1] = sum_j ksc(j) V[j][d2] K[j][d1]
__global__ __launch_bounds__(256) void dAT_kernel()
{
    const int bid  = blockIdx.x;
    const int bc   = bid >> 2;
    const int tile = bid & 3;
    const int b = bc >> 6, c = bc & 63;
    const int t0  = c * CH;
    const int d1b = (tile & 1) * 128;
    const int d2b = (tile >> 1) * 128;

    __shared__ float Ks[32][128];
    __shared__ float Vs[32][128];

    const int tid = threadIdx.x;
    const int tx = tid & 15, ty = tid >> 4;
    const int lrow = tid >> 3;
    const int lc4  = (tid & 7) * 4;

    ull acc[8][4];
#pragma unroll
    for (int r = 0; r < 8; r++)
#pragma unroll
        for (int p = 0; p < 4; p++) acc[r][p] = 0ull;

    for (int jt = 0; jt < 2; jt++) {
        const float ksc = powf(DECAYC, (float)(CH - 1 - (jt * 32 + lrow)));
        const size_t rbase = ((size_t)(b * SEQ + t0 + jt * 32 + lrow)) * DIMN;
        float4 kv[4], vv[4];
#pragma unroll
        for (int u = 0; u < 4; u++) {
            kv[u] = *(const float4*)(g_k + rbase + d1b + lc4 + u * 32);
            vv[u] = *(const float4*)(g_v + rbase + d2b + lc4 + u * 32);
        }
        __syncthreads();
#pragma unroll
        for (int u = 0; u < 4; u++) {
            const int col = lc4 + u * 32;
            Ks[lrow][col + 0] = kv[u].x * ksc;
            Ks[lrow][col + 1] = kv[u].y * ksc;
            Ks[lrow][col + 2] = kv[u].z * ksc;
            Ks[lrow][col + 3] = kv[u].w * ksc;
            *(float4*)&Vs[lrow][col] = vv[u];
        }
        __syncthreads();
#pragma unroll
        for (int j = 0; j < 32; j++) {
            float4 va = *(const float4*)&Vs[j][ty * 8];
            float4 vb = *(const float4*)&Vs[j][ty * 8 + 4];
            float4 ka = *(const float4*)&Ks[j][tx * 8];
            float4 kb = *(const float4*)&Ks[j][tx * 8 + 4];
            ull kp[4] = { pack2(ka.x, ka.y), pack2(ka.z, ka.w),
                          pack2(kb.x, kb.y), pack2(kb.z, kb.w) };
            float vr[8] = { va.x, va.y, va.z, va.w, vb.x, vb.y, vb.z, vb.w };
#pragma unroll
            for (int r = 0; r < 8; r++) {
                ull vd = pack2(vr[r], vr[r]);
#pragma unroll
                for (int p = 0; p < 4; p++)
                    acc[r][p] = fma2(vd, kp[p], acc[r][p]);
            }
        }
    }

    const size_t obase = ((size_t)(b * NC + c)) * DIMN * DIMN;
#pragma unroll
    for (int r = 0; r < 8; r++) {
        float f[8];
        unpack2(acc[r][0], f[0], f[1]);
        unpack2(acc[r][1], f[2], f[3]);
        unpack2(acc[r][2], f[4], f[5]);
        unpack2(acc[r][3], f[6], f[7]);
        float* p = g_dAT + obase + (size_t)(d2b + ty * 8 + r) * DIMN + d1b + tx * 8;
        *(float4*)(p)     = make_float4(f[0], f[1], f[2], f[3]);
        *(float4*)(p + 4) = make_float4(f[4], f[5], f[6], f[7]);
    }
}

// ---------------- state combine (transposed): AsT prefix, bf16 split -------
__global__ __launch_bounds__(256) void state_combine_kernel(
    const float* __restrict__ st_in, float* __restrict__ st_out)
{
    const int idx = blockIdx.x * 256 + threadIdx.x;
    const int b = idx >> 16;
    const int e = idx & 65535;
    const int te = ((e & 255) << 8) | (e >> 8);
    float A = st_in[(size_t)b * 65536 + te];
    const float lc = 0.00117901845f;   // 0.9^64
    const size_t base = ((size_t)b * NC) * 65536 + e;
#pragma unroll 4
    for (int c = 0; c < NC; c++) {
        __nv_bfloat16 h = __float2bfloat16(A);
        g_AsThi[base + (size_t)c * 65536] = h;
        g_AsTlo[base + (size_t)c * 65536] = __float2bfloat16(A - __bfloat162float(h));
        A = lc * A + g_dAT[base + (size_t)c * 65536];
    }
    if (st_out) st_out[(size_t)b * 65536 + te] = A;
}

// ---------------- y_inter via HMMA: Y += lam^(i+1) Q @ A_prev --------------
// Also emits final y as bf16 hi/lo (feeds output projection).
#define YI_SMEM ((2*64 + 2*256) * ASTR * 2)   // 92160 bytes

__global__ __launch_bounds__(256, 2) void y_inter_hmma_kernel()
{
    extern __shared__ __align__(16) __nv_bfloat16 smem[];
    __nv_bfloat16* sQhi = smem;
    __nv_bfloat16* sQlo = smem + 64 * ASTR;
    __nv_bfloat16* sBhi = smem + 2 * 64 * ASTR;
    __nv_bfloat16* sBlo = smem + 2 * 64 * ASTR + 256 * ASTR;

    const int b  = blockIdx.x >> 6;
    const int c  = blockIdx.x & 63;
    const int t0 = c * CH;

    const int tid  = threadIdx.x;
    const int wid  = tid >> 5;
    const int lane = tid & 31;
    const int gId  = lane >> 2;
    const int tig  = lane & 3;
    const int wm0 = (wid & 1) * 32;
    const int wn0 = (wid >> 1) * 64;

    const size_t Abase = ((size_t)(b * NC + c)) * 65536;

    float acc[2][8][4];
#pragma unroll
    for (int i = 0; i < 2; i++)
#pragma unroll
        for (int j = 0; j < 8; j++)
#pragma unroll
            for (int r = 0; r < 4; r++) acc[i][j][r] = 0.0f;

    for (int kc = 0; kc < 4; kc++) {
        __syncthreads();
        {
            const int row = tid >> 2;
            const int seg = tid & 3;
            const size_t gq = ((size_t)(b * SEQ + t0 + row)) * DIMN + kc * 64 + seg * 16;
#pragma unroll
            for (int u = 0; u < 2; u++) {
                *(uint4*)(sQhi + row * ASTR + seg * 16 + u * 8)
                    = *(const uint4*)(g_qhi + gq + u * 8);
                *(uint4*)(sQlo + row * ASTR + seg * 16 + u * 8)
                    = *(const uint4*)(g_qlo + gq + u * 8);
            }
        }
        {
            const int u = tid & 7;
            const int rbase = tid >> 3;
#pragma unroll
            for (int w = 0; w < 8; w++) {
                const int row = w * 32 + rbase;
                const size_t gofs = Abase + (size_t)row * DIMN + kc * 64 + u * 8;
                *(uint4*)(sBhi + row * ASTR + u * 8) = *(const uint4*)(g_AsThi + gofs);
                *(uint4*)(sBlo + row * ASTR + u * 8) = *(const uint4*)(g_AsTlo + gofs);
            }
        }
        __syncthreads();

#pragma unroll
        for (int kk = 0; kk < 4; kk++) {
            const int k0 = kk * 16 + tig * 2;
            uint32_t ah[2][4], al[2][4];
#pragma unroll
            for (int i = 0; i < 2; i++) {
                const int r0 = wm0 + i * 16 + gId;
                ah[i][0] = *(const uint32_t*)(sQhi + r0 * ASTR + k0);
                ah[i][1] = *(const uint32_t*)(sQhi + (r0 + 8) * ASTR + k0);
                ah[i][2] = *(const uint32_t*)(sQhi + r0 * ASTR + k0 + 8);
                ah[i][3] = *(const uint32_t*)(sQhi + (r0 + 8) * ASTR + k0 + 8);
                al[i][0] = *(const uint32_t*)(sQlo + r0 * ASTR + k0);
                al[i][1] = *(const uint32_t*)(sQlo + (r0 + 8) * ASTR + k0);
                al[i][2] = *(const uint32_t*)(sQlo + r0 * ASTR + k0 + 8);
                al[i][3] = *(const uint32_t*)(sQlo + (r0 + 8) * ASTR + k0 + 8);
            }
#pragma unroll
            for (int j = 0; j < 8; j++) {
                const int nr = wn0 + j * 8 + gId;
                uint32_t bh[2], bl[2];
                bh[0] = *(const uint32_t*)(sBhi + nr * ASTR + k0);
                bh[1] = *(const uint32_t*)(sBhi + nr * ASTR + k0 + 8);
                bl[0] = *(const uint32_t*)(sBlo + nr * ASTR + k0);
                bl[1] = *(const uint32_t*)(sBlo + nr * ASTR + k0 + 8);
                mma16816(acc[0][j], ah[0], bh);
                mma16816(acc[0][j], ah[0], bl);
                mma16816(acc[0][j], al[0], bh);
                mma16816(acc[1][j], ah[1], bh);
                mma16816(acc[1][j], ah[1], bl);
                mma16816(acc[1][j], al[1], bh);
            }
        }
    }

    // epilogue: scale by lam^(i+1), add to g_y, emit final y bf16 split
    const size_t ybase = ((size_t)(b * SEQ + t0)) * DIMN;
#pragma unroll
    for (int i = 0; i < 2; i++) {
        const int r0 = wm0 + i * 16 + gId;
        const float s0 = powf(DECAYC, (float)(r0 + 1));
        const float s1 = powf(DECAYC, (float)(r0 + 9));
#pragma unroll
        for (int j = 0; j < 8; j++) {
            const int col = wn0 + j * 8 + tig * 2;
            float* p0 = g_y + ybase + (size_t)r0 * DIMN + col;
            float* p1 = g_y + ybase + (size_t)(r0 + 8) * DIMN + col;
            float2 o0 = *(float2*)p0;
            float2 o1 = *(float2*)p1;
            o0.x += s0 * acc[i][j][0]; o0.y += s0 * acc[i][j][1];
            o1.x += s1 * acc[i][j][2]; o1.y += s1 * acc[i][j][3];
            *(float2*)p0 = o0;
            *(float2*)p1 = o1;

            const size_t e0 = ybase + (size_t)r0 * DIMN + col;
            const size_t e1 = ybase + (size_t)(r0 + 8) * DIMN + col;
            __nv_bfloat16 h0 = __float2bfloat16(o0.x);
            __nv_bfloat16 h1 = __float2bfloat16(o0.y);
            __nv_bfloat16 h2 = __float2bfloat16(o1.x);
            __nv_bfloat16 h3 = __float2bfloat16(o1.y);
            *(__nv_bfloat162*)(g_yhi + e0) = __nv_bfloat162(h0, h1);
            *(__nv_bfloat162*)(g_yhi + e1) = __nv_bfloat162(h2, h3);
            *(__nv_bfloat162*)(g_ylo + e0)
                = __nv_bfloat162(__float2bfloat16(o0.x - __bfloat162float(h0)),
                                 __float2bfloat16(o0.y - __bfloat162float(h1)));
            *(__nv_bfloat162*)(g_ylo + e1)
                = __nv_bfloat162(__float2bfloat16(o1.x - __bfloat162float(h2)),
                                 __float2bfloat16(o1.y - __bfloat162float(h3)));
        }
    }
}

// ---------------- launch ---------------------------------------------------
extern "C" void kernel_launch(void* const* d_in, const int* in_sizes, int n_in,
                              void* d_out, int out_size)
{
    const float* x  = (const float*)d_in[0];
    const float* st = (const float*)d_in[1];
    const float* Wk = (const float*)d_in[2];
    const float* bk = (const float*)d_in[3];
    const float* Wv = (const float*)d_in[4];
    const float* bv = (const float*)d_in[5];
    const float* Wq = (const float*)d_in[6];
    const float* bq = (const float*)d_in[7];
    const float* Wo = (const float*)d_in[8];
    const float* bo = (const float*)d_in[9];

    float* out = (float*)d_out;
    float* state_out = nullptr;
    const long long need = (long long)BATCH * SEQ * DIMN + (long long)BATCH * DIMN * DIMN;
    if ((long long)out_size >= need)
        state_out = out + (size_t)BATCH * SEQ * DIMN;

    void *p;
    cudaGetSymbolAddress(&p, g_k);   float* pk = (float*)p;
    cudaGetSymbolAddress(&p, g_v);   float* pv = (float*)p;
    cudaGetSymbolAddress(&p, g_q);   float* pq = (float*)p;
    cudaGetSymbolAddress(&p, g_xhi); __nv_bfloat16* pxh = (__nv_bfloat16*)p;
    cudaGetSymbolAddress(&p, g_xlo); __nv_bfloat16* pxl = (__nv_bfloat16*)p;
    cudaGetSymbolAddress(&p, g_yhi); __nv_bfloat16* pyh = (__nv_bfloat16*)p;
    cudaGetSymbolAddress(&p, g_ylo); __nv_bfloat16* pyl = (__nv_bfloat16*)p;
    cudaGetSymbolAddress(&p, g_qhi); __nv_bfloat16* pqh = (__nv_bfloat16*)p;
    cudaGetSymbolAddress(&p, g_qlo); __nv_bfloat16* pql = (__nv_bfloat16*)p;
    cudaGetSymbolAddress(&p, g_khi); __nv_bfloat16* pkh = (__nv_bfloat16*)p;
    cudaGetSymbolAddress(&p, g_klo); __nv_bfloat16* pkl = (__nv_bfloat16*)p;
    cudaGetSymbolAddress(&p, g_whi); __nv_bfloat16* pwh = (__nv_bfloat16*)p;
    cudaGetSymbolAddress(&p, g_wlo); __nv_bfloat16* pwl = (__nv_bfloat16*)p;

    cudaFuncSetAttribute(hmma_gemm_kernel,
                         cudaFuncAttributeMaxDynamicSharedMemorySize, HG_SMEM);
    cudaFuncSetAttribute(attn_local_kernel,
                         cudaFuncAttributeMaxDynamicSharedMemorySize, AL_SMEM);
    cudaFuncSetAttribute(y_inter_hmma_kernel,
                         cudaFuncAttributeMaxDynamicSharedMemorySize, YI_SMEM);

    const int WSZ = DIMN * DIMN;          // 65536
    const int XN4 = MTOT * DIMN / 4;      // 2097152

    // split conversions
    conv_split_kernel<<<(XN4 + 255) / 256, 256>>>(x, pxh, pxl, XN4);
    conv_split_kernel<<<WSZ / 4 / 256, 256>>>(Wk, pwh + 0 * WSZ, pwl + 0 * WSZ, WSZ / 4);
    conv_split_kernel<<<WSZ / 4 / 256, 256>>>(Wv, pwh + 1 * WSZ, pwl + 1 * WSZ, WSZ / 4);
    conv_split_kernel<<<WSZ / 4 / 256, 256>>>(Wq, pwh + 2 * WSZ, pwl + 2 * WSZ, WSZ / 4);
    conv_split_kernel<<<WSZ / 4 / 256, 256>>>(Wo, pwh + 3 * WSZ, pwl + 3 * WSZ, WSZ / 4);

    dim3 ggrid(MTOT / 128, 2);

    // projections (k pre-scaled by eta = LR; k and q emit bf16 splits)
    hmma_gemm_kernel<<<ggrid, 256, HG_SMEM>>>(pxh, pxl, pwh + 0 * WSZ, pwl + 0 * WSZ,
                                              bk, pk, LRC, pkh, pkl);
    hmma_gemm_kernel<<<ggrid, 256, HG_SMEM>>>(pxh, pxl, pwh + 1 * WSZ, pwl + 1 * WSZ,
                                              bv, pv, 1.0f, nullptr, nullptr);
    hmma_gemm_kernel<<<ggrid, 256, HG_SMEM>>>(pxh, pxl, pwh + 2 * WSZ, pwl + 2 * WSZ,
                                              bq, pq, 1.0f, pqh, pql);

    // chunked scan path
    attn_local_kernel<<<BATCH * NC, 256, AL_SMEM>>>();        // Y_intra -> g_y
    dAT_kernel<<<BATCH * NC * 4, 256>>>();                    // dA^T per chunk
    state_combine_kernel<<<2048, 256>>>(st, state_out);       // prefix -> AsT bf16
    y_inter_hmma_kernel<<<BATCH * NC, 256, YI_SMEM>>>();      // g_y += lam Q@A, emit split

    // output projection (reads split emitted by y_inter)
    hmma_gemm_kernel<<<ggrid, 256, HG_SMEM>>>(pyh, pyl, pwh + 3 * WSZ, pwl + 3 * WSZ,
                                              bo, out, 1.0f, nullptr, nullptr);
}

// round 12
// speedup vs baseline: 1.4879x; 1.0648x over previous
#include <cuda_runtime.h>
#include <cuda_bf16.h>
#include <cstdint>
#include <math.h>

#define DIMN   256
#define BATCH  8
#define SEQ    4096
#define LRC    0.1f
#define DECAYC 0.9f
#define MTOT   (BATCH*SEQ)          // 32768
#define CH     64                   // chunk length
#define NC     (SEQ/CH)             // 64 chunks

// ---------------- scratch (device globals: allocation-free) ----------------
__device__ float g_v[BATCH*SEQ*DIMN];   // v fp32 (attn_local phase2)
__device__ float g_y[BATCH*SEQ*DIMN];   // y_intra fp32 (attn_local -> y_inter)
__device__ float g_dAT[BATCH*NC*DIMN*DIMN];           // per-chunk dA^T [d2][d1]
__device__ __nv_bfloat16 g_AsThi[BATCH*NC*DIMN*DIMN]; // prefix state^T hi
__device__ __nv_bfloat16 g_AsTlo[BATCH*NC*DIMN*DIMN]; // prefix state^T lo

__device__ __nv_bfloat16 g_xhi[MTOT*DIMN];
__device__ __nv_bfloat16 g_xlo[MTOT*DIMN];
__device__ __nv_bfloat16 g_yhi[MTOT*DIMN];   // final y split (y_inter epilogue)
__device__ __nv_bfloat16 g_ylo[MTOT*DIMN];
__device__ __nv_bfloat16 g_qhi[MTOT*DIMN];   // q split (q-GEMM epilogue)
__device__ __nv_bfloat16 g_qlo[MTOT*DIMN];
__device__ __nv_bfloat16 g_khi[MTOT*DIMN];   // eta-k split (k-GEMM epilogue)
__device__ __nv_bfloat16 g_klo[MTOT*DIMN];
__device__ __nv_bfloat16 g_kdhi[MTOT*DIMN];  // lam^(63-j)*eta-k split
__device__ __nv_bfloat16 g_kdlo[MTOT*DIMN];
__device__ __nv_bfloat16 g_vhi[MTOT*DIMN];   // v split (v-GEMM epilogue)
__device__ __nv_bfloat16 g_vlo[MTOT*DIMN];
__device__ __nv_bfloat16 g_whi[4*DIMN*DIMN];
__device__ __nv_bfloat16 g_wlo[4*DIMN*DIMN];

// ---------------- packed f32x2 helpers (Blackwell FFMA2) -------------------
typedef unsigned long long ull;

__device__ __forceinline__ ull pack2(float lo, float hi) {
    ull r; asm("mov.b64 %0,{%1,%2};" : "=l"(r) : "f"(lo), "f"(hi)); return r;
}
__device__ __forceinline__ void unpack2(ull p, float& lo, float& hi) {
    asm("mov.b64 {%0,%1},%2;" : "=f"(lo), "=f"(hi) : "l"(p));
}
__device__ __forceinline__ ull fma2(ull a, ull b, ull c) {
    ull d; asm("fma.rn.f32x2 %0,%1,%2,%3;" : "=l"(d) : "l"(a), "l"(b), "l"(c)); return d;
}

// ---------------- split conversion: fp32 -> bf16 hi + bf16 lo --------------
__global__ __launch_bounds__(256) void conv_split_kernel(
    const float* __restrict__ in, __nv_bfloat16* __restrict__ hi,
    __nv_bfloat16* __restrict__ lo, int n4)
{
    int i = blockIdx.x * 256 + threadIdx.x;
    if (i >= n4) return;
    float4 v = ((const float4*)in)[i];
    __nv_bfloat16 h0 = __float2bfloat16(v.x);
    __nv_bfloat16 h1 = __float2bfloat16(v.y);
    __nv_bfloat16 h2 = __float2bfloat16(v.z);
    __nv_bfloat16 h3 = __float2bfloat16(v.w);
    __nv_bfloat16 l0 = __float2bfloat16(v.x - __bfloat162float(h0));
    __nv_bfloat16 l1 = __float2bfloat16(v.y - __bfloat162float(h1));
    __nv_bfloat16 l2 = __float2bfloat16(v.z - __bfloat162float(h2));
    __nv_bfloat16 l3 = __float2bfloat16(v.w - __bfloat162float(h3));
    __nv_bfloat162* hp = (__nv_bfloat162*)hi;
    __nv_bfloat162* lp = (__nv_bfloat162*)lo;
    hp[2 * i]     = __nv_bfloat162(h0, h1);
    hp[2 * i + 1] = __nv_bfloat162(h2, h3);
    lp[2 * i]     = __nv_bfloat162(l0, l1);
    lp[2 * i + 1] = __nv_bfloat162(l2, l3);
}

// ---------------- HMMA primitives ------------------------------------------
#define ASTR 72                    // smem row stride in bf16 (144B)

__device__ __forceinline__ void mma16816(float* c, const uint32_t* a, const uint32_t* b) {
    asm volatile(
        "mma.sync.aligned.m16n8k16.row.col.f32.bf16.bf16.f32 "
        "{%0,%1,%2,%3}, {%4,%5,%6,%7}, {%8,%9}, {%0,%1,%2,%3};"
        : "+f"(c[0]), "+f"(c[1]), "+f"(c[2]), "+f"(c[3])
        : "r"(a[0]), "r"(a[1]), "r"(a[2]), "r"(a[3]), "r"(b[0]), "r"(b[1]));
}

__device__ __forceinline__ void ldsm4t(uint32_t* r, uint32_t addr) {
    asm volatile("ldmatrix.sync.aligned.m8n8.x4.trans.shared.b16 {%0,%1,%2,%3}, [%4];"
        : "=r"(r[0]), "=r"(r[1]), "=r"(r[2]), "=r"(r[3]) : "r"(addr));
}

// split-store helper (float2 -> hi/lo bf16x2)
__device__ __forceinline__ void split_store(__nv_bfloat16* hi, __nv_bfloat16* lo,
                                            size_t idx, float a, float b) {
    __nv_bfloat16 h0 = __float2bfloat16(a);
    __nv_bfloat16 h1 = __float2bfloat16(b);
    *(__nv_bfloat162*)(hi + idx) = __nv_bfloat162(h0, h1);
    *(__nv_bfloat162*)(lo + idx)
        = __nv_bfloat162(__float2bfloat16(a - __bfloat162float(h0)),
                         __float2bfloat16(b - __bfloat162float(h1)));
}

// ---------------- HMMA GEMM: C = alpha*(A @ W^T + bias) --------------------
// Optional: C fp32, Chi/Clo split of C, Dhi/Dlo split of lam^(63-(row&63))*C.
#define HG_SMEM (4 * 128 * ASTR * 2)   // 73728 bytes

__global__ __launch_bounds__(256, 2) void hmma_gemm_kernel(
    const __nv_bfloat16* __restrict__ Ahi, const __nv_bfloat16* __restrict__ Alo,
    const __nv_bfloat16* __restrict__ Whi, const __nv_bfloat16* __restrict__ Wlo,
    const float* __restrict__ bias, float* __restrict__ C, float alpha,
    __nv_bfloat16* __restrict__ Chi, __nv_bfloat16* __restrict__ Clo,
    __nv_bfloat16* __restrict__ Dhi, __nv_bfloat16* __restrict__ Dlo)
{
    extern __shared__ __align__(16) __nv_bfloat16 smem[];
    __nv_bfloat16* sAhi = smem;
    __nv_bfloat16* sAlo = smem + 128 * ASTR;
    __nv_bfloat16* sBhi = smem + 2 * 128 * ASTR;
    __nv_bfloat16* sBlo = smem + 3 * 128 * ASTR;

    const int tid  = threadIdx.x;
    const int wid  = tid >> 5;
    const int lane = tid & 31;
    const int gId  = lane >> 2;
    const int tig  = lane & 3;
    const int mBase = blockIdx.x * 128;
    const int nBase = blockIdx.y * 128;
    const int wm0 = (wid & 3) * 32;
    const int wn0 = (wid >> 2) * 64;

    float acc[2][8][4];
#pragma unroll
    for (int i = 0; i < 2; i++)
#pragma unroll
        for (int j = 0; j < 8; j++)
#pragma unroll
            for (int r = 0; r < 4; r++) acc[i][j][r] = 0.0f;

    const int lrow = tid >> 1;
    const int lhalf = tid & 1;

    for (int kc = 0; kc < 4; kc++) {
        __syncthreads();
        {
            const size_t ga = (size_t)(mBase + lrow) * DIMN + kc * 64 + lhalf * 32;
            const size_t gb = (size_t)(nBase + lrow) * DIMN + kc * 64 + lhalf * 32;
            const uint4* pah = (const uint4*)(Ahi + ga);
            const uint4* pal = (const uint4*)(Alo + ga);
            const uint4* pbh = (const uint4*)(Whi + gb);
            const uint4* pbl = (const uint4*)(Wlo + gb);
            __nv_bfloat16* dA = sAhi + lrow * ASTR + lhalf * 32;
            __nv_bfloat16* dAl = sAlo + lrow * ASTR + lhalf * 32;
            __nv_bfloat16* dB = sBhi + lrow * ASTR + lhalf * 32;
            __nv_bfloat16* dBl = sBlo + lrow * ASTR + lhalf * 32;
#pragma unroll
            for (int u = 0; u < 4; u++) {
                *(uint4*)(dA + u * 8)  = pah[u];
                *(uint4*)(dAl + u * 8) = pal[u];
                *(uint4*)(dB + u * 8)  = pbh[u];
                *(uint4*)(dBl + u * 8) = pbl[u];
            }
        }
        __syncthreads();

#pragma unroll
        for (int kk = 0; kk < 4; kk++) {
            const int k0 = kk * 16 + tig * 2;
            uint32_t ah[2][4], al[2][4];
#pragma unroll
            for (int i = 0; i < 2; i++) {
                const int r0 = wm0 + i * 16 + gId;
                ah[i][0] = *(const uint32_t*)(sAhi + r0 * ASTR + k0);
                ah[i][1] = *(const uint32_t*)(sAhi + (r0 + 8) * ASTR + k0);
                ah[i][2] = *(const uint32_t*)(sAhi + r0 * ASTR + k0 + 8);
                ah[i][3] = *(const uint32_t*)(sAhi + (r0 + 8) * ASTR + k0 + 8);
                al[i][0] = *(const uint32_t*)(sAlo + r0 * ASTR + k0);
                al[i][1] = *(const uint32_t*)(sAlo + (r0 + 8) * ASTR + k0);
                al[i][2] = *(const uint32_t*)(sAlo + r0 * ASTR + k0 + 8);
                al[i][3] = *(const uint32_t*)(sAlo + (r0 + 8) * ASTR + k0 + 8);
            }
#pragma unroll
            for (int j = 0; j < 8; j++) {
                const int nr = wn0 + j * 8 + gId;
                uint32_t bh[2], bl[2];
                bh[0] = *(const uint32_t*)(sBhi + nr * ASTR + k0);
                bh[1] = *(const uint32_t*)(sBhi + nr * ASTR + k0 + 8);
                bl[0] = *(const uint32_t*)(sBlo + nr * ASTR + k0);
                bl[1] = *(const uint32_t*)(sBlo + nr * ASTR + k0 + 8);
                mma16816(acc[0][j], ah[0], bh);
                mma16816(acc[0][j], ah[0], bl);
                mma16816(acc[0][j], al[0], bh);
                mma16816(acc[1][j], ah[1], bh);
                mma16816(acc[1][j], ah[1], bl);
                mma16816(acc[1][j], al[1], bh);
            }
        }
    }

#pragma unroll
    for (int i = 0; i < 2; i++) {
        const int r0 = mBase + wm0 + i * 16 + gId;
        float s0 = 0.0f, s1 = 0.0f;
        if (Dhi) {
            s0 = powf(DECAYC, (float)(63 - (r0 & 63)));
            s1 = powf(DECAYC, (float)(63 - ((r0 + 8) & 63)));
        }
#pragma unroll
        for (int j = 0; j < 8; j++) {
            const int col = nBase + wn0 + j * 8 + tig * 2;
            const float b0 = bias[col], b1 = bias[col + 1];
            float2 o0 = make_float2(alpha * (acc[i][j][0] + b0),
                                    alpha * (acc[i][j][1] + b1));
            float2 o1 = make_float2(alpha * (acc[i][j][2] + b0),
                                    alpha * (acc[i][j][3] + b1));
            const size_t e0 = (size_t)r0 * DIMN + col;
            const size_t e1 = (size_t)(r0 + 8) * DIMN + col;
            if (C) {
                *(float2*)(C + e0) = o0;
                *(float2*)(C + e1) = o1;
            }
            if (Chi) {
                split_store(Chi, Clo, e0, o0.x, o0.y);
                split_store(Chi, Clo, e1, o1.x, o1.y);
            }
            if (Dhi) {
                split_store(Dhi, Dlo, e0, o0.x * s0, o0.y * s0);
                split_store(Dhi, Dlo, e1, o1.x * s1, o1.y * s1);
            }
        }
    }
}

// ---------------- attn_local: phase1 HMMA (S=QK^T), phase2 FFMA2 (S@V) -----
#define AL_SSOFF (4 * 64 * ASTR)
#define AL_SMEM  (4*64*ASTR*2 + 64*68*4 + 64*64*4)   // 70656 bytes

__global__ __launch_bounds__(256, 2) void attn_local_kernel()
{
    extern __shared__ __align__(16) __nv_bfloat16 smem[];
    __nv_bfloat16* sQhi = smem;
    __nv_bfloat16* sQlo = smem + 64 * ASTR;
    __nv_bfloat16* sKhi = smem + 2 * 64 * ASTR;
    __nv_bfloat16* sKlo = smem + 3 * 64 * ASTR;
    float* Ss = (float*)(smem + AL_SSOFF);     // [64][68] layout [j][i]
    float* Vs = Ss + 64 * 68;                  // [64][64] layout [j][d]

    const int b  = blockIdx.x >> 6;
    const int c  = blockIdx.x & 63;
    const int t0 = c * CH;
    const int tid  = threadIdx.x;
    const int wid  = tid >> 5;
    const int lane = tid & 31;
    const int gId  = lane >> 2;
    const int tig  = lane & 3;
    const int wm0 = (wid & 1) * 32;
    const int wn0 = (wid >> 1) * 16;

    float acc[2][2][4];
#pragma unroll
    for (int i = 0; i < 2; i++)
#pragma unroll
        for (int j = 0; j < 2; j++)
#pragma unroll
            for (int r = 0; r < 4; r++) acc[i][j][r] = 0.0f;

    const int lrw = tid >> 2;
    const int seg = tid & 3;

    for (int kc = 0; kc < 4; kc++) {
        __syncthreads();
        {
            const size_t g = ((size_t)(b * SEQ + t0 + lrw)) * DIMN + kc * 64 + seg * 16;
#pragma unroll
            for (int u = 0; u < 2; u++) {
                *(uint4*)(sQhi + lrw * ASTR + seg * 16 + u * 8) = *(const uint4*)(g_qhi + g + u * 8);
                *(uint4*)(sQlo + lrw * ASTR + seg * 16 + u * 8) = *(const uint4*)(g_qlo + g + u * 8);
                *(uint4*)(sKhi + lrw * ASTR + seg * 16 + u * 8) = *(const uint4*)(g_khi + g + u * 8);
                *(uint4*)(sKlo + lrw * ASTR + seg * 16 + u * 8) = *(const uint4*)(g_klo + g + u * 8);
            }
        }
        __syncthreads();

#pragma unroll
        for (int kk = 0; kk < 4; kk++) {
            const int k0 = kk * 16 + tig * 2;
            uint32_t ah[2][4], al[2][4];
#pragma unroll
            for (int i = 0; i < 2; i++) {
                const int r0 = wm0 + i * 16 + gId;
                ah[i][0] = *(const uint32_t*)(sQhi + r0 * ASTR + k0);
                ah[i][1] = *(const uint32_t*)(sQhi + (r0 + 8) * ASTR + k0);
                ah[i][2] = *(const uint32_t*)(sQhi + r0 * ASTR + k0 + 8);
                ah[i][3] = *(const uint32_t*)(sQhi + (r0 + 8) * ASTR + k0 + 8);
                al[i][0] = *(const uint32_t*)(sQlo + r0 * ASTR + k0);
                al[i][1] = *(const uint32_t*)(sQlo + (r0 + 8) * ASTR + k0);
                al[i][2] = *(const uint32_t*)(sQlo + r0 * ASTR + k0 + 8);
                al[i][3] = *(const uint32_t*)(sQlo + (r0 + 8) * ASTR + k0 + 8);
            }
#pragma unroll
            for (int jt = 0; jt < 2; jt++) {
                const int nr = wn0 + jt * 8 + gId;
                uint32_t bh[2], bl[2];
                bh[0] = *(const uint32_t*)(sKhi + nr * ASTR + k0);
                bh[1] = *(const uint32_t*)(sKhi + nr * ASTR + k0 + 8);
                bl[0] = *(const uint32_t*)(sKlo + nr * ASTR + k0);
                bl[1] = *(const uint32_t*)(sKlo + nr * ASTR + k0 + 8);
                mma16816(acc[0][jt], ah[0], bh);
                mma16816(acc[0][jt], ah[0], bl);
                mma16816(acc[0][jt], al[0], bh);
                mma16816(acc[1][jt], ah[1], bh);
                mma16816(acc[1][jt], ah[1], bl);
                mma16816(acc[1][jt], al[1], bh);
            }
        }
    }

    {
        float li[2][2], lj[2][2];
#pragma unroll
        for (int it = 0; it < 2; it++) {
            const int i1 = wm0 + it * 16 + gId;
            li[it][0] = powf(DECAYC, (float)i1);
            li[it][1] = powf(DECAYC, (float)(i1 + 8));
        }
#pragma unroll
        for (int jt = 0; jt < 2; jt++) {
            const int j1 = wn0 + jt * 8 + tig * 2;
            lj[jt][0] = powf(DECAYC, -(float)j1);
            lj[jt][1] = powf(DECAYC, -(float)(j1 + 1));
        }
#pragma unroll
        for (int it = 0; it < 2; it++) {
            const int i1 = wm0 + it * 16 + gId;
            const int i2 = i1 + 8;
#pragma unroll
            for (int jt = 0; jt < 2; jt++) {
                const int j1 = wn0 + jt * 8 + tig * 2;
                const int j2 = j1 + 1;
                Ss[j1 * 68 + i1] = (j1 <= i1) ? acc[it][jt][0] * li[it][0] * lj[jt][0] : 0.0f;
                Ss[j2 * 68 + i1] = (j2 <= i1) ? acc[it][jt][1] * li[it][0] * lj[jt][1] : 0.0f;
                Ss[j1 * 68 + i2] = (j1 <= i2) ? acc[it][jt][2] * li[it][1] * lj[jt][0] : 0.0f;
                Ss[j2 * 68 + i2] = (j2 <= i2) ? acc[it][jt][3] * li[it][1] * lj[jt][1] : 0.0f;
            }
        }
    }

    const int tx = tid & 15, ty = tid >> 4;
    const int i0 = ty * 4;
    const int lc4 = (tid & 3) * 4;
    const size_t rowbase = ((size_t)(b * SEQ + t0 + lrw)) * DIMN;
    const size_t ybase   = ((size_t)(b * SEQ + t0)) * DIMN;

    for (int nt = 0; nt < 4; nt++) {
        float4 vv[4];
#pragma unroll
        for (int u = 0; u < 4; u++)
            vv[u] = *(const float4*)(g_v + rowbase + nt * 64 + lc4 + u * 16);
        __syncthreads();
#pragma unroll
        for (int u = 0; u < 4; u++)
            *(float4*)&Vs[lrw * 64 + lc4 + u * 16] = vv[u];
        __syncthreads();

        ull y2[4][2];
#pragma unroll
        for (int r = 0; r < 4; r++) { y2[r][0] = 0ull; y2[r][1] = 0ull; }
#pragma unroll
        for (int j = 0; j < 64; j++) {
            float4 s4 = *(const float4*)&Ss[j * 68 + i0];
            float4 v4 = *(const float4*)&Vs[j * 64 + tx * 4];
            ull vp0 = pack2(v4.x, v4.y), vp1 = pack2(v4.z, v4.w);
            float sr[4] = { s4.x, s4.y, s4.z, s4.w };
#pragma unroll
            for (int r = 0; r < 4; r++) {
                ull sb2 = pack2(sr[r], sr[r]);
                y2[r][0] = fma2(sb2, vp0, y2[r][0]);
                y2[r][1] = fma2(sb2, vp1, y2[r][1]);
            }
        }
#pragma unroll
        for (int r = 0; r < 4; r++) {
            float a, bb2, cc, dd;
            unpack2(y2[r][0], a, bb2);
            unpack2(y2[r][1], cc, dd);
            *(float4*)(g_y + ybase + (size_t)(i0 + r) * DIMN + nt * 64 + tx * 4)
                = make_float4(a, bb2, cc, dd);
        }
    }
}

// ---------------- dA^T via HMMA + ldmatrix.trans ---------------------------
// dAT[d2][d1] = sum_j V[j][d2] * Kd[j][d1], Kd = lam^(63-j)*eta*k (pre-split).
// grid: B*NC*4 quads (128x128 out tile), K=64. smem holds [j][d] bf16 splits.
#define VSTR 136                                  // 272B rows, ldmatrix conflict-free
#define DAT_SMEM (4 * 64 * VSTR * 2)              // 69632 bytes

__global__ __launch_bounds__(256, 2) void dAT_hmma_kernel()
{
    extern __shared__ __align__(16) __nv_bfloat16 smem[];
    __nv_bfloat16* sVhi = smem;                   // [j][d2]
    __nv_bfloat16* sVlo = smem + 64 * VSTR;
    __nv_bfloat16* sKhi = smem + 2 * 64 * VSTR;   // [j][d1]
    __nv_bfloat16* sKlo = smem + 3 * 64 * VSTR;

    const int bid  = blockIdx.x;
    const int quad = bid & 3;
    const int bc   = bid >> 2;
    const int b = bc >> 6, c = bc & 63;
    const int t0  = c * CH;
    const int d2b = (quad & 1) * 128;
    const int d1b = (quad >> 1) * 128;

    const int tid  = threadIdx.x;
    const int wid  = tid >> 5;
    const int lane = tid & 31;
    const int gId  = lane >> 2;
    const int tig  = lane & 3;
    const int wm0 = (wid & 3) * 32;    // d2
    const int wn0 = (wid >> 2) * 64;   // d1

    // vectorized fill: 4 threads per j-row, 32 bf16 (4 x uint4) each per array
    {
        const int j = tid >> 2, part = tid & 3;
        const size_t gr = ((size_t)(b * SEQ + t0 + j)) * DIMN;
        const __nv_bfloat16* pvh = g_vhi + gr + d2b + part * 32;
        const __nv_bfloat16* pvl = g_vlo + gr + d2b + part * 32;
        const __nv_bfloat16* pkh = g_kdhi + gr + d1b + part * 32;
        const __nv_bfloat16* pkl = g_kdlo + gr + d1b + part * 32;
        __nv_bfloat16* dvh = sVhi + j * VSTR + part * 32;
        __nv_bfloat16* dvl = sVlo + j * VSTR + part * 32;
        __nv_bfloat16* dkh = sKhi + j * VSTR + part * 32;
        __nv_bfloat16* dkl = sKlo + j * VSTR + part * 32;
#pragma unroll
        for (int u = 0; u < 4; u++) {
            *(uint4*)(dvh + u * 8) = *(const uint4*)(pvh + u * 8);
            *(uint4*)(dvl + u * 8) = *(const uint4*)(pvl + u * 8);
            *(uint4*)(dkh + u * 8) = *(const uint4*)(pkh + u * 8);
            *(uint4*)(dkl + u * 8) = *(const uint4*)(pkl + u * 8);
        }
    }
    __syncthreads();

    const uint32_t svhi = (uint32_t)__cvta_generic_to_shared(sVhi);
    const uint32_t svlo = (uint32_t)__cvta_generic_to_shared(sVlo);
    const uint32_t skhi = (uint32_t)__cvta_generic_to_shared(sKhi);
    const uint32_t sklo = (uint32_t)__cvta_generic_to_shared(sKlo);

    const int l8 = lane & 7;
    const int arow = ((lane >> 4) & 1) * 8 + l8;   // A: matrices 0,1 k0-7; 2,3 k8-15
    const int acol = ((lane >> 3) & 1) * 8;        //    matrices 0,2 m0-7; 1,3 m8-15
    const int brow = ((lane >> 3) & 1) * 8 + l8;   // B: matrices 0,2 k0-7; 1,3 k8-15
    const int bcol = ((lane >> 4) & 1) * 8;        //    matrices 0,1 n0-7; 2,3 n8-15

    float acc[2][8][4];
#pragma unroll
    for (int i = 0; i < 2; i++)
#pragma unroll
        for (int j = 0; j < 8; j++)
#pragma unroll
            for (int r = 0; r < 4; r++) acc[i][j][r] = 0.0f;

#pragma unroll
    for (int kk = 0; kk < 4; kk++) {
        const int j0 = kk * 16;
        uint32_t ah[2][4], al[2][4];
#pragma unroll
        for (int it = 0; it < 2; it++) {
            const int d2c = wm0 + it * 16;
            const uint32_t off = (uint32_t)(((j0 + arow) * VSTR + d2c + acol) * 2);
            ldsm4t(ah[it], svhi + off);
            ldsm4t(al[it], svlo + off);
        }
#pragma unroll
        for (int jp = 0; jp < 4; jp++) {
            const int d1c = wn0 + jp * 16;
            const uint32_t boff = (uint32_t)(((j0 + brow) * VSTR + d1c + bcol) * 2);
            uint32_t bh[4], bl[4];
            ldsm4t(bh, skhi + boff);
            ldsm4t(bl, sklo + boff);
            mma16816(acc[0][jp * 2],     ah[0], bh);
            mma16816(acc[0][jp * 2],     ah[0], bl);
            mma16816(acc[0][jp * 2],     al[0], bh);
            mma16816(acc[1][jp * 2],     ah[1], bh);
            mma16816(acc[1][jp * 2],     ah[1], bl);
            mma16816(acc[1][jp * 2],     al[1], bh);
            mma16816(acc[0][jp * 2 + 1], ah[0], bh + 2);
            mma16816(acc[0][jp * 2 + 1], ah[0], bl + 2);
            mma16816(acc[0][jp * 2 + 1], al[0], bh + 2);
            mma16816(acc[1][jp * 2 + 1], ah[1], bh + 2);
            mma16816(acc[1][jp * 2 + 1], ah[1], bl + 2);
            mma16816(acc[1][jp * 2 + 1], al[1], bh + 2);
        }
    }

    const size_t obase = ((size_t)(b * NC + c)) * DIMN * DIMN;
#pragma unroll
    for (int it = 0; it < 2; it++) {
        const int r0 = d2b + wm0 + it * 16 + gId;
#pragma unroll
        for (int jn = 0; jn < 8; jn++) {
            const int col = d1b + wn0 + jn * 8 + tig * 2;
            *(float2*)(g_dAT + obase + (size_t)r0 * DIMN + col)
                = make_float2(acc[it][jn][0], acc[it][jn][1]);
            *(float2*)(g_dAT + obase + (size_t)(r0 + 8) * DIMN + col)
                = make_float2(acc[it][jn][2], acc[it][jn][3]);
        }
    }
}

// ---------------- state combine (transposed): AsT prefix, bf16 split -------
__global__ __launch_bounds__(256) void state_combine_kernel(
    const float* __restrict__ st_in, float* __restrict__ st_out)
{
    const int idx = blockIdx.x * 256 + threadIdx.x;
    const int b = idx >> 16;
    const int e = idx & 65535;
    const int te = ((e & 255) << 8) | (e >> 8);
    float A = st_in[(size_t)b * 65536 + te];
    const float lc = 0.00117901845f;   // 0.9^64
    const size_t base = ((size_t)b * NC) * 65536 + e;
#pragma unroll 4
    for (int c = 0; c < NC; c++) {
        __nv_bfloat16 h = __float2bfloat16(A);
        g_AsThi[base + (size_t)c * 65536] = h;
        g_AsTlo[base + (size_t)c * 65536] = __float2bfloat16(A - __bfloat162float(h));
        A = lc * A + g_dAT[base + (size_t)c * 65536];
    }
    if (st_out) st_out[(size_t)b * 65536 + te] = A;
}

// ---------------- y_inter via HMMA: y = y_intra + lam^(i+1) Q @ A_prev -----
// Emits final y only as bf16 hi/lo split (feeds output projection).
#define YI_SMEM ((2*64 + 2*256) * ASTR * 2)   // 92160 bytes

__global__ __launch_bounds__(256, 2) void y_inter_hmma_kernel()
{
    extern __shared__ __align__(16) __nv_bfloat16 smem[];
    __nv_bfloat16* sQhi = smem;
    __nv_bfloat16* sQlo = smem + 64 * ASTR;
    __nv_bfloat16* sBhi = smem + 2 * 64 * ASTR;
    __nv_bfloat16* sBlo = smem + 2 * 64 * ASTR + 256 * ASTR;

    const int b  = blockIdx.x >> 6;
    const int c  = blockIdx.x & 63;
    const int t0 = c * CH;

    const int tid  = threadIdx.x;
    const int wid  = tid >> 5;
    const int lane = tid & 31;
    const int gId  = lane >> 2;
    const int tig  = lane & 3;
    const int wm0 = (wid & 1) * 32;
    const int wn0 = (wid >> 1) * 64;

    const size_t Abase = ((size_t)(b * NC + c)) * 65536;

    float acc[2][8][4];
#pragma unroll
    for (int i = 0; i < 2; i++)
#pragma unroll
        for (int j = 0; j < 8; j++)
#pragma unroll
            for (int r = 0; r < 4; r++) acc[i][j][r] = 0.0f;

    for (int kc = 0; kc < 4; kc++) {
        __syncthreads();
        {
            const int row = tid >> 2;
            const int seg = tid & 3;
            const size_t gq = ((size_t)(b * SEQ + t0 + row)) * DIMN + kc * 64 + seg * 16;
#pragma unroll
            for (int u = 0; u < 2; u++) {
                *(uint4*)(sQhi + row * ASTR + seg * 16 + u * 8)
                    = *(const uint4*)(g_qhi + gq + u * 8);
                *(uint4*)(sQlo + row * ASTR + seg * 16 + u * 8)
                    = *(const uint4*)(g_qlo + gq + u * 8);
            }
        }
        {
            const int u = tid & 7;
            const int rbase = tid >> 3;
#pragma unroll
            for (int w = 0; w < 8; w++) {
                const int row = w * 32 + rbase;
                const size_t gofs = Abase + (size_t)row * DIMN + kc * 64 + u * 8;
                *(uint4*)(sBhi + row * ASTR + u * 8) = *(const uint4*)(g_AsThi + gofs);
                *(uint4*)(sBlo + row * ASTR + u * 8) = *(const uint4*)(g_AsTlo + gofs);
            }
        }
        __syncthreads();

#pragma unroll
        for (int kk = 0; kk < 4; kk++) {
            const int k0 = kk * 16 + tig * 2;
            uint32_t ah[2][4], al[2][4];
#pragma unroll
            for (int i = 0; i < 2; i++) {
                const int r0 = wm0 + i * 16 + gId;
                ah[i][0] = *(const uint32_t*)(sQhi + r0 * ASTR + k0);
                ah[i][1] = *(const uint32_t*)(sQhi + (r0 + 8) * ASTR + k0);
                ah[i][2] = *(const uint32_t*)(sQhi + r0 * ASTR + k0 + 8);
                ah[i][3] = *(const uint32_t*)(sQhi + (r0 + 8) * ASTR + k0 + 8);
                al[i][0] = *(const uint32_t*)(sQlo + r0 * ASTR + k0);
                al[i][1] = *(const uint32_t*)(sQlo + (r0 + 8) * ASTR + k0);
                al[i][2] = *(const uint32_t*)(sQlo + r0 * ASTR + k0 + 8);
                al[i][3] = *(const uint32_t*)(sQlo + (r0 + 8) * ASTR + k0 + 8);
            }
#pragma unroll
            for (int j = 0; j < 8; j++) {
                const int nr = wn0 + j * 8 + gId;
                uint32_t bh[2], bl[2];
                bh[0] = *(const uint32_t*)(sBhi + nr * ASTR + k0);
                bh[1] = *(const uint32_t*)(sBhi + nr * ASTR + k0 + 8);
                bl[0] = *(const uint32_t*)(sBlo + nr * ASTR + k0);
                bl[1] = *(const uint32_t*)(sBlo + nr * ASTR + k0 + 8);
                mma16816(acc[0][j], ah[0], bh);
                mma16816(acc[0][j], ah[0], bl);
                mma16816(acc[0][j], al[0], bh);
                mma16816(acc[1][j], ah[1], bh);
                mma16816(acc[1][j], ah[1], bl);
                mma16816(acc[1][j], al[1], bh);
            }
        }
    }

    const size_t ybase = ((size_t)(b * SEQ + t0)) * DIMN;
#pragma unroll
    for (int i = 0; i < 2; i++) {
        const int r0 = wm0 + i * 16 + gId;
        const float s0 = powf(DECAYC, (float)(r0 + 1));
        const float s1 = powf(DECAYC, (float)(r0 + 9));
#pragma unroll
        for (int j = 0; j < 8; j++) {
            const int col = wn0 + j * 8 + tig * 2;
            const size_t e0 = ybase + (size_t)r0 * DIMN + col;
            const size_t e1 = ybase + (size_t)(r0 + 8) * DIMN + col;
            float2 o0 = *(float2*)(g_y + e0);
            float2 o1 = *(float2*)(g_y + e1);
            o0.x += s0 * acc[i][j][0]; o0.y += s0 * acc[i][j][1];
            o1.x += s1 * acc[i][j][2]; o1.y += s1 * acc[i][j][3];
            split_store(g_yhi, g_ylo, e0, o0.x, o0.y);
            split_store(g_yhi, g_ylo, e1, o1.x, o1.y);
        }
    }
}

// ---------------- launch ---------------------------------------------------
extern "C" void kernel_launch(void* const* d_in, const int* in_sizes, int n_in,
                              void* d_out, int out_size)
{
    const float* x  = (const float*)d_in[0];
    const float* st = (const float*)d_in[1];
    const float* Wk = (const float*)d_in[2];
    const float* bk = (const float*)d_in[3];
    const float* Wv = (const float*)d_in[4];
    const float* bv = (const float*)d_in[5];
    const float* Wq = (const float*)d_in[6];
    const float* bq = (const float*)d_in[7];
    const float* Wo = (const float*)d_in[8];
    const float* bo = (const float*)d_in[9];

    float* out = (float*)d_out;
    float* state_out = nullptr;
    const long long need = (long long)BATCH * SEQ * DIMN + (long long)BATCH * DIMN * DIMN;
    if ((long long)out_size >= need)
        state_out = out + (size_t)BATCH * SEQ * DIMN;

    void *p;
    cudaGetSymbolAddress(&p, g_v);    float* pv = (float*)p;
    cudaGetSymbolAddress(&p, g_xhi);  __nv_bfloat16* pxh = (__nv_bfloat16*)p;
    cudaGetSymbolAddress(&p, g_xlo);  __nv_bfloat16* pxl = (__nv_bfloat16*)p;
    cudaGetSymbolAddress(&p, g_yhi);  __nv_bfloat16* pyh = (__nv_bfloat16*)p;
    cudaGetSymbolAddress(&p, g_ylo);  __nv_bfloat16* pyl = (__nv_bfloat16*)p;
    cudaGetSymbolAddress(&p, g_qhi);  __nv_bfloat16* pqh = (__nv_bfloat16*)p;
    cudaGetSymbolAddress(&p, g_qlo);  __nv_bfloat16* pql = (__nv_bfloat16*)p;
    cudaGetSymbolAddress(&p, g_khi);  __nv_bfloat16* pkh = (__nv_bfloat16*)p;
    cudaGetSymbolAddress(&p, g_klo);  __nv_bfloat16* pkl = (__nv_bfloat16*)p;
    cudaGetSymbolAddress(&p, g_kdhi); __nv_bfloat16* pkdh = (__nv_bfloat16*)p;
    cudaGetSymbolAddress(&p, g_kdlo); __nv_bfloat16* pkdl = (__nv_bfloat16*)p;
    cudaGetSymbolAddress(&p, g_vhi);  __nv_bfloat16* pvh = (__nv_bfloat16*)p;
    cudaGetSymbolAddress(&p, g_vlo);  __nv_bfloat16* pvl = (__nv_bfloat16*)p;
    cudaGetSymbolAddress(&p, g_whi);  __nv_bfloat16* pwh = (__nv_bfloat16*)p;
    cudaGetSymbolAddress(&p, g_wlo);  __nv_bfloat16* pwl = (__nv_bfloat16*)p;

    cudaFuncSetAttribute(hmma_gemm_kernel,
                         cudaFuncAttributeMaxDynamicSharedMemorySize, HG_SMEM);
    cudaFuncSetAttribute(attn_local_kernel,
                         cudaFuncAttributeMaxDynamicSharedMemorySize, AL_SMEM);
    cudaFuncSetAttribute(dAT_hmma_kernel,
                         cudaFuncAttributeMaxDynamicSharedMemorySize, DAT_SMEM);
    cudaFuncSetAttribute(y_inter_hmma_kernel,
                         cudaFuncAttributeMaxDynamicSharedMemorySize, YI_SMEM);

    const int WSZ = DIMN * DIMN;          // 65536
    const int XN4 = MTOT * DIMN / 4;      // 2097152

    // split conversions (x + weights)
    conv_split_kernel<<<(XN4 + 255) / 256, 256>>>(x, pxh, pxl, XN4);
    conv_split_kernel<<<WSZ / 4 / 256, 256>>>(Wk, pwh + 0 * WSZ, pwl + 0 * WSZ, WSZ / 4);
    conv_split_kernel<<<WSZ / 4 / 256, 256>>>(Wv, pwh + 1 * WSZ, pwl + 1 * WSZ, WSZ / 4);
    conv_split_kernel<<<WSZ / 4 / 256, 256>>>(Wq, pwh + 2 * WSZ, pwl + 2 * WSZ, WSZ / 4);
    conv_split_kernel<<<WSZ / 4 / 256, 256>>>(Wo, pwh + 3 * WSZ, pwl + 3 * WSZ, WSZ / 4);

    dim3 ggrid(MTOT / 128, 2);

    // projections: k emits split + decay-scaled split; v emits fp32 + split;
    // q emits split only
    hmma_gemm_kernel<<<ggrid, 256, HG_SMEM>>>(pxh, pxl, pwh + 0 * WSZ, pwl + 0 * WSZ,
                                              bk, nullptr, LRC, pkh, pkl, pkdh, pkdl);
    hmma_gemm_kernel<<<ggrid, 256, HG_SMEM>>>(pxh, pxl, pwh + 1 * WSZ, pwl + 1 * WSZ,
                                              bv, pv, 1.0f, pvh, pvl, nullptr, nullptr);
    hmma_gemm_kernel<<<ggrid, 256, HG_SMEM>>>(pxh, pxl, pwh + 2 * WSZ, pwl + 2 * WSZ,
                                              bq, nullptr, 1.0f, pqh, pql, nullptr, nullptr);

    // chunked scan path
    attn_local_kernel<<<BATCH * NC, 256, AL_SMEM>>>();          // Y_intra -> g_y
    dAT_hmma_kernel<<<BATCH * NC * 4, 256, DAT_SMEM>>>();       // dA^T per chunk (HMMA)
    state_combine_kernel<<<2048, 256>>>(st, state_out);         // prefix -> AsT bf16
    y_inter_hmma_kernel<<<BATCH * NC, 256, YI_SMEM>>>();        // final y split

    // output projection (reads y split)
    hmma_gemm_kernel<<<ggrid, 256, HG_SMEM>>>(pyh, pyl, pwh + 3 * WSZ, pwl + 3 * WSZ,
                                              bo, out, 1.0f, nullptr, nullptr,
                                              nullptr, nullptr);
}

// round 16
// speedup vs baseline: 1.5323x; 1.0299x over previous
#include <cuda_runtime.h>
#include <cuda_bf16.h>
#include <cstdint>
#include <math.h>

#define DIMN   256
#define BATCH  8
#define SEQ    4096
#define LRC    0.1f
#define DECAYC 0.9f
#define MTOT   (BATCH*SEQ)          // 32768
#define CH     64                   // chunk length
#define NC     (SEQ/CH)             // 64 chunks

// ---------------- scratch (device globals: allocation-free) ----------------
__device__ float g_v[BATCH*SEQ*DIMN];   // v fp32 (attn_local phase2)
__device__ float g_y[BATCH*SEQ*DIMN];   // y_intra fp32 (attn_local -> y_inter)
__device__ float g_dAT[BATCH*NC*DIMN*DIMN];           // per-chunk dA^T [d2][d1]
__device__ __nv_bfloat16 g_AsThi[BATCH*NC*DIMN*DIMN]; // prefix state^T hi
__device__ __nv_bfloat16 g_AsTlo[BATCH*NC*DIMN*DIMN]; // prefix state^T lo

__device__ __nv_bfloat16 g_yhi[MTOT*DIMN];   // final y split (y_inter epilogue)
__device__ __nv_bfloat16 g_ylo[MTOT*DIMN];
__device__ __nv_bfloat16 g_qhi[MTOT*DIMN];   // q split (q-GEMM epilogue)
__device__ __nv_bfloat16 g_qlo[MTOT*DIMN];
__device__ __nv_bfloat16 g_khi[MTOT*DIMN];   // eta-k split (k-GEMM epilogue)
__device__ __nv_bfloat16 g_klo[MTOT*DIMN];
__device__ __nv_bfloat16 g_kdhi[MTOT*DIMN];  // lam^(63-j)*eta-k split
__device__ __nv_bfloat16 g_kdlo[MTOT*DIMN];
__device__ __nv_bfloat16 g_vhi[MTOT*DIMN];   // v split (v-GEMM epilogue)
__device__ __nv_bfloat16 g_vlo[MTOT*DIMN];
__device__ __nv_bfloat16 g_whi[4*DIMN*DIMN];
__device__ __nv_bfloat16 g_wlo[4*DIMN*DIMN];

// ---------------- packed f32x2 helpers (Blackwell FFMA2) -------------------
typedef unsigned long long ull;

__device__ __forceinline__ ull pack2(float lo, float hi) {
    ull r; asm("mov.b64 %0,{%1,%2};" : "=l"(r) : "f"(lo), "f"(hi)); return r;
}
__device__ __forceinline__ void unpack2(ull p, float& lo, float& hi) {
    asm("mov.b64 {%0,%1},%2;" : "=f"(lo), "=f"(hi) : "l"(p));
}
__device__ __forceinline__ ull fma2(ull a, ull b, ull c) {
    ull d; asm("fma.rn.f32x2 %0,%1,%2,%3;" : "=l"(d) : "l"(a), "l"(b), "l"(c)); return d;
}

// ---------------- split helpers --------------------------------------------
__device__ __forceinline__ void split_store(__nv_bfloat16* hi, __nv_bfloat16* lo,
                                            size_t idx, float a, float b) {
    __nv_bfloat16 h0 = __float2bfloat16(a);
    __nv_bfloat16 h1 = __float2bfloat16(b);
    *(__nv_bfloat162*)(hi + idx) = __nv_bfloat162(h0, h1);
    *(__nv_bfloat162*)(lo + idx)
        = __nv_bfloat162(__float2bfloat16(a - __bfloat162float(h0)),
                         __float2bfloat16(b - __bfloat162float(h1)));
}

// split 8 consecutive floats into one uint4 of hi and one of lo (smem dest)
__device__ __forceinline__ void split8_smem(const float* f,
                                            __nv_bfloat16* dh, __nv_bfloat16* dl) {
    __align__(16) __nv_bfloat162 hh[4];
    __align__(16) __nv_bfloat162 ll[4];
#pragma unroll
    for (int e = 0; e < 4; e++) {
        float a = f[2 * e], b = f[2 * e + 1];
        __nv_bfloat16 h0 = __float2bfloat16(a);
        __nv_bfloat16 h1 = __float2bfloat16(b);
        hh[e] = __nv_bfloat162(h0, h1);
        ll[e] = __nv_bfloat162(__float2bfloat16(a - __bfloat162float(h0)),
                               __float2bfloat16(b - __bfloat162float(h1)));
    }
    *(uint4*)dh = *(const uint4*)hh;
    *(uint4*)dl = *(const uint4*)ll;
}

// ---------------- fused weight split: 4 weights, one launch ----------------
__global__ __launch_bounds__(256) void conv_split_w4_kernel(
    const float* __restrict__ W0, const float* __restrict__ W1,
    const float* __restrict__ W2, const float* __restrict__ W3,
    __nv_bfloat16* __restrict__ hi, __nv_bfloat16* __restrict__ lo)
{
    const int i = blockIdx.x * 256 + threadIdx.x;      // float4 index, 0..65535
    const int w = i >> 14;
    const int r = i & 16383;
    const float* src = (w == 0) ? W0 : (w == 1) ? W1 : (w == 2) ? W2 : W3;
    float4 v = ((const float4*)src)[r];
    split_store(hi, lo, (size_t)i * 4,     v.x, v.y);
    split_store(hi, lo, (size_t)i * 4 + 2, v.z, v.w);
}

// ---------------- HMMA primitives ------------------------------------------
#define ASTR 72                    // smem row stride in bf16 (144B)

__device__ __forceinline__ void mma16816(float* c, const uint32_t* a, const uint32_t* b) {
    asm volatile(
        "mma.sync.aligned.m16n8k16.row.col.f32.bf16.bf16.f32 "
        "{%0,%1,%2,%3}, {%4,%5,%6,%7}, {%8,%9}, {%0,%1,%2,%3};"
        : "+f"(c[0]), "+f"(c[1]), "+f"(c[2]), "+f"(c[3])
        : "r"(a[0]), "r"(a[1]), "r"(a[2]), "r"(a[3]), "r"(b[0]), "r"(b[1]));
}

__device__ __forceinline__ void ldsm4t(uint32_t* r, uint32_t addr) {
    asm volatile("ldmatrix.sync.aligned.m8n8.x4.trans.shared.b16 {%0,%1,%2,%3}, [%4];"
        : "=r"(r[0]), "=r"(r[1]), "=r"(r[2]), "=r"(r[3]) : "r"(addr));
}

// ---------------- HMMA GEMM: C = alpha*(A @ W^T + bias) --------------------
// A source: Afp fp32 (in-register split) OR Ahi/Alo pre-split.
// Per-z job: weights, bias, outputs. grid (M/128, 2, nz).
struct GemmJob {
    const __nv_bfloat16 *Whi, *Wlo;
    const float* bias;
    float* C;
    __nv_bfloat16 *Chi, *Clo, *Dhi, *Dlo;
    float alpha;
};
struct GemmJobs { GemmJob j[3]; };

#define HG_SMEM (4 * 128 * ASTR * 2)   // 73728 bytes

__global__ __launch_bounds__(256, 2) void hmma_gemm_kernel(
    const float* __restrict__ Afp,
    const __nv_bfloat16* __restrict__ Ahi, const __nv_bfloat16* __restrict__ Alo,
    GemmJobs jobs)
{
    extern __shared__ __align__(16) __nv_bfloat16 smem[];
    __nv_bfloat16* sAhi = smem;
    __nv_bfloat16* sAlo = smem + 128 * ASTR;
    __nv_bfloat16* sBhi = smem + 2 * 128 * ASTR;
    __nv_bfloat16* sBlo = smem + 3 * 128 * ASTR;

    const GemmJob job = jobs.j[blockIdx.z];

    const int tid  = threadIdx.x;
    const int wid  = tid >> 5;
    const int lane = tid & 31;
    const int gId  = lane >> 2;
    const int tig  = lane & 3;
    const int mBase = blockIdx.x * 128;
    const int nBase = blockIdx.y * 128;
    const int wm0 = (wid & 3) * 32;
    const int wn0 = (wid >> 2) * 64;

    float acc[2][8][4];
#pragma unroll
    for (int i = 0; i < 2; i++)
#pragma unroll
        for (int j = 0; j < 8; j++)
#pragma unroll
            for (int r = 0; r < 4; r++) acc[i][j][r] = 0.0f;

    const int lrow = tid >> 1;
    const int lhalf = tid & 1;

    for (int kc = 0; kc < 4; kc++) {
        __syncthreads();
        {
            const size_t ga = (size_t)(mBase + lrow) * DIMN + kc * 64 + lhalf * 32;
            const size_t gb = (size_t)(nBase + lrow) * DIMN + kc * 64 + lhalf * 32;
            __nv_bfloat16* dA  = sAhi + lrow * ASTR + lhalf * 32;
            __nv_bfloat16* dAl = sAlo + lrow * ASTR + lhalf * 32;
            if (Afp) {
                // fp32 A: split in registers (k-contiguous, fully vectorized)
                const float* pa = Afp + ga;
#pragma unroll
                for (int u = 0; u < 4; u++) {
                    float f[8];
                    float4 f0 = *(const float4*)(pa + u * 8);
                    float4 f1 = *(const float4*)(pa + u * 8 + 4);
                    f[0]=f0.x; f[1]=f0.y; f[2]=f0.z; f[3]=f0.w;
                    f[4]=f1.x; f[5]=f1.y; f[6]=f1.z; f[7]=f1.w;
                    split8_smem(f, dA + u * 8, dAl + u * 8);
                }
            } else {
                const uint4* pah = (const uint4*)(Ahi + ga);
                const uint4* pal = (const uint4*)(Alo + ga);
#pragma unroll
                for (int u = 0; u < 4; u++) {
                    *(uint4*)(dA + u * 8)  = pah[u];
                    *(uint4*)(dAl + u * 8) = pal[u];
                }
            }
            const uint4* pbh = (const uint4*)(job.Whi + gb);
            const uint4* pbl = (const uint4*)(job.Wlo + gb);
            __nv_bfloat16* dB  = sBhi + lrow * ASTR + lhalf * 32;
            __nv_bfloat16* dBl = sBlo + lrow * ASTR + lhalf * 32;
#pragma unroll
            for (int u = 0; u < 4; u++) {
                *(uint4*)(dB + u * 8)  = pbh[u];
                *(uint4*)(dBl + u * 8) = pbl[u];
            }
        }
        __syncthreads();

#pragma unroll
        for (int kk = 0; kk < 4; kk++) {
            const int k0 = kk * 16 + tig * 2;
            uint32_t ah[2][4], al[2][4];
#pragma unroll
            for (int i = 0; i < 2; i++) {
                const int r0 = wm0 + i * 16 + gId;
                ah[i][0] = *(const uint32_t*)(sAhi + r0 * ASTR + k0);
                ah[i][1] = *(const uint32_t*)(sAhi + (r0 + 8) * ASTR + k0);
                ah[i][2] = *(const uint32_t*)(sAhi + r0 * ASTR + k0 + 8);
                ah[i][3] = *(const uint32_t*)(sAhi + (r0 + 8) * ASTR + k0 + 8);
                al[i][0] = *(const uint32_t*)(sAlo + r0 * ASTR + k0);
                al[i][1] = *(const uint32_t*)(sAlo + (r0 + 8) * ASTR + k0);
                al[i][2] = *(const uint32_t*)(sAlo + r0 * ASTR + k0 + 8);
                al[i][3] = *(const uint32_t*)(sAlo + (r0 + 8) * ASTR + k0 + 8);
            }
#pragma unroll
            for (int j = 0; j < 8; j++) {
                const int nr = wn0 + j * 8 + gId;
                uint32_t bh[2], bl[2];
                bh[0] = *(const uint32_t*)(sBhi + nr * ASTR + k0);
                bh[1] = *(const uint32_t*)(sBhi + nr * ASTR + k0 + 8);
                bl[0] = *(const uint32_t*)(sBlo + nr * ASTR + k0);
                bl[1] = *(const uint32_t*)(sBlo + nr * ASTR + k0 + 8);
                mma16816(acc[0][j], ah[0], bh);
                mma16816(acc[0][j], ah[0], bl);
                mma16816(acc[0][j], al[0], bh);
                mma16816(acc[1][j], ah[1], bh);
                mma16816(acc[1][j], ah[1], bl);
                mma16816(acc[1][j], al[1], bh);
            }
        }
    }

#pragma unroll
    for (int i = 0; i < 2; i++) {
        const int r0 = mBase + wm0 + i * 16 + gId;
        float s0 = 0.0f, s1 = 0.0f;
        if (job.Dhi) {
            s0 = powf(DECAYC, (float)(63 - (r0 & 63)));
            s1 = powf(DECAYC, (float)(63 - ((r0 + 8) & 63)));
        }
#pragma unroll
        for (int j = 0; j < 8; j++) {
            const int col = nBase + wn0 + j * 8 + tig * 2;
            const float b0 = job.bias[col], b1 = job.bias[col + 1];
            float2 o0 = make_float2(job.alpha * (acc[i][j][0] + b0),
                                    job.alpha * (acc[i][j][1] + b1));
            float2 o1 = make_float2(job.alpha * (acc[i][j][2] + b0),
                                    job.alpha * (acc[i][j][3] + b1));
            const size_t e0 = (size_t)r0 * DIMN + col;
            const size_t e1 = (size_t)(r0 + 8) * DIMN + col;
            if (job.C) {
                *(float2*)(job.C + e0) = o0;
                *(float2*)(job.C + e1) = o1;
            }
            if (job.Chi) {
                split_store(job.Chi, job.Clo, e0, o0.x, o0.y);
                split_store(job.Chi, job.Clo, e1, o1.x, o1.y);
            }
            if (job.Dhi) {
                split_store(job.Dhi, job.Dlo, e0, o0.x * s0, o0.y * s0);
                split_store(job.Dhi, job.Dlo, e1, o1.x * s1, o1.y * s1);
            }
        }
    }
}

// ---------------- attn_local: phase1 HMMA (S=QK^T), phase2 FFMA2 (S@V) -----
#define AL_SSOFF (4 * 64 * ASTR)
#define AL_SMEM  (4*64*ASTR*2 + 64*68*4 + 64*64*4)   // 70656 bytes

__global__ __launch_bounds__(256, 2) void attn_local_kernel()
{
    extern __shared__ __align__(16) __nv_bfloat16 smem[];
    __nv_bfloat16* sQhi = smem;
    __nv_bfloat16* sQlo = smem + 64 * ASTR;
    __nv_bfloat16* sKhi = smem + 2 * 64 * ASTR;
    __nv_bfloat16* sKlo = smem + 3 * 64 * ASTR;
    float* Ss = (float*)(smem + AL_SSOFF);     // [64][68] layout [j][i]
    float* Vs = Ss + 64 * 68;                  // [64][64] layout [j][d]

    const int b  = blockIdx.x >> 6;
    const int c  = blockIdx.x & 63;
    const int t0 = c * CH;
    const int tid  = threadIdx.x;
    const int wid  = tid >> 5;
    const int lane = tid & 31;
    const int gId  = lane >> 2;
    const int tig  = lane & 3;
    const int wm0 = (wid & 1) * 32;
    const int wn0 = (wid >> 1) * 16;

    float acc[2][2][4];
#pragma unroll
    for (int i = 0; i < 2; i++)
#pragma unroll
        for (int j = 0; j < 2; j++)
#pragma unroll
            for (int r = 0; r < 4; r++) acc[i][j][r] = 0.0f;

    const int lrw = tid >> 2;
    const int seg = tid & 3;

    for (int kc = 0; kc < 4; kc++) {
        __syncthreads();
        {
            const size_t g = ((size_t)(b * SEQ + t0 + lrw)) * DIMN + kc * 64 + seg * 16;
#pragma unroll
            for (int u = 0; u < 2; u++) {
                *(uint4*)(sQhi + lrw * ASTR + seg * 16 + u * 8) = *(const uint4*)(g_qhi + g + u * 8);
                *(uint4*)(sQlo + lrw * ASTR + seg * 16 + u * 8) = *(const uint4*)(g_qlo + g + u * 8);
                *(uint4*)(sKhi + lrw * ASTR + seg * 16 + u * 8) = *(const uint4*)(g_khi + g + u * 8);
                *(uint4*)(sKlo + lrw * ASTR + seg * 16 + u * 8) = *(const uint4*)(g_klo + g + u * 8);
            }
        }
        __syncthreads();

#pragma unroll
        for (int kk = 0; kk < 4; kk++) {
            const int k0 = kk * 16 + tig * 2;
            uint32_t ah[2][4], al[2][4];
#pragma unroll
            for (int i = 0; i < 2; i++) {
                const int r0 = wm0 + i * 16 + gId;
                ah[i][0] = *(const uint32_t*)(sQhi + r0 * ASTR + k0);
                ah[i][1] = *(const uint32_t*)(sQhi + (r0 + 8) * ASTR + k0);
                ah[i][2] = *(const uint32_t*)(sQhi + r0 * ASTR + k0 + 8);
                ah[i][3] = *(const uint32_t*)(sQhi + (r0 + 8) * ASTR + k0 + 8);
                al[i][0] = *(const uint32_t*)(sQlo + r0 * ASTR + k0);
                al[i][1] = *(const uint32_t*)(sQlo + (r0 + 8) * ASTR + k0);
                al[i][2] = *(const uint32_t*)(sQlo + r0 * ASTR + k0 + 8);
                al[i][3] = *(const uint32_t*)(sQlo + (r0 + 8) * ASTR + k0 + 8);
            }
#pragma unroll
            for (int jt = 0; jt < 2; jt++) {
                const int nr = wn0 + jt * 8 + gId;
                uint32_t bh[2], bl[2];
                bh[0] = *(const uint32_t*)(sKhi + nr * ASTR + k0);
                bh[1] = *(const uint32_t*)(sKhi + nr * ASTR + k0 + 8);
                bl[0] = *(const uint32_t*)(sKlo + nr * ASTR + k0);
                bl[1] = *(const uint32_t*)(sKlo + nr * ASTR + k0 + 8);
                mma16816(acc[0][jt], ah[0], bh);
                mma16816(acc[0][jt], ah[0], bl);
                mma16816(acc[0][jt], al[0], bh);
                mma16816(acc[1][jt], ah[1], bh);
                mma16816(acc[1][jt], ah[1], bl);
                mma16816(acc[1][jt], al[1], bh);
            }
        }
    }

    {
        float li[2][2], lj[2][2];
#pragma unroll
        for (int it = 0; it < 2; it++) {
            const int i1 = wm0 + it * 16 + gId;
            li[it][0] = powf(DECAYC, (float)i1);
            li[it][1] = powf(DECAYC, (float)(i1 + 8));
        }
#pragma unroll
        for (int jt = 0; jt < 2; jt++) {
            const int j1 = wn0 + jt * 8 + tig * 2;
            lj[jt][0] = powf(DECAYC, -(float)j1);
            lj[jt][1] = powf(DECAYC, -(float)(j1 + 1));
        }
#pragma unroll
        for (int it = 0; it < 2; it++) {
            const int i1 = wm0 + it * 16 + gId;
            const int i2 = i1 + 8;
#pragma unroll
            for (int jt = 0; jt < 2; jt++) {
                const int j1 = wn0 + jt * 8 + tig * 2;
                const int j2 = j1 + 1;
                Ss[j1 * 68 + i1] = (j1 <= i1) ? acc[it][jt][0] * li[it][0] * lj[jt][0] : 0.0f;
                Ss[j2 * 68 + i1] = (j2 <= i1) ? acc[it][jt][1] * li[it][0] * lj[jt][1] : 0.0f;
                Ss[j1 * 68 + i2] = (j1 <= i2) ? acc[it][jt][2] * li[it][1] * lj[jt][0] : 0.0f;
                Ss[j2 * 68 + i2] = (j2 <= i2) ? acc[it][jt][3] * li[it][1] * lj[jt][1] : 0.0f;
            }
        }
    }

    const int tx = tid & 15, ty = tid >> 4;
    const int i0 = ty * 4;
    const int lc4 = (tid & 3) * 4;
    const size_t rowbase = ((size_t)(b * SEQ + t0 + lrw)) * DIMN;
    const size_t ybase   = ((size_t)(b * SEQ + t0)) * DIMN;

    for (int nt = 0; nt < 4; nt++) {
        float4 vv[4];
#pragma unroll
        for (int u = 0; u < 4; u++)
            vv[u] = *(const float4*)(g_v + rowbase + nt * 64 + lc4 + u * 16);
        __syncthreads();
#pragma unroll
        for (int u = 0; u < 4; u++)
            *(float4*)&Vs[lrw * 64 + lc4 + u * 16] = vv[u];
        __syncthreads();

        ull y2[4][2];
#pragma unroll
        for (int r = 0; r < 4; r++) { y2[r][0] = 0ull; y2[r][1] = 0ull; }
#pragma unroll
        for (int j = 0; j < 64; j++) {
            float4 s4 = *(const float4*)&Ss[j * 68 + i0];
            float4 v4 = *(const float4*)&Vs[j * 64 + tx * 4];
            ull vp0 = pack2(v4.x, v4.y), vp1 = pack2(v4.z, v4.w);
            float sr[4] = { s4.x, s4.y, s4.z, s4.w };
#pragma unroll
            for (int r = 0; r < 4; r++) {
                ull sb2 = pack2(sr[r], sr[r]);
                y2[r][0] = fma2(sb2, vp0, y2[r][0]);
                y2[r][1] = fma2(sb2, vp1, y2[r][1]);
            }
        }
#pragma unroll
        for (int r = 0; r < 4; r++) {
            float a, bb2, cc, dd;
            unpack2(y2[r][0], a, bb2);
            unpack2(y2[r][1], cc, dd);
            *(float4*)(g_y + ybase + (size_t)(i0 + r) * DIMN + nt * 64 + tx * 4)
                = make_float4(a, bb2, cc, dd);
        }
    }
}

// ---------------- dA^T via HMMA + ldmatrix.trans ---------------------------
#define VSTR 136                                  // 272B rows, ldmatrix conflict-free
#define DAT_SMEM (4 * 64 * VSTR * 2)              // 69632 bytes

__global__ __launch_bounds__(256, 2) void dAT_hmma_kernel()
{
    extern __shared__ __align__(16) __nv_bfloat16 smem[];
    __nv_bfloat16* sVhi = smem;                   // [j][d2]
    __nv_bfloat16* sVlo = smem + 64 * VSTR;
    __nv_bfloat16* sKhi = smem + 2 * 64 * VSTR;   // [j][d1]
    __nv_bfloat16* sKlo = smem + 3 * 64 * VSTR;

    const int bid  = blockIdx.x;
    const int quad = bid & 3;
    const int bc   = bid >> 2;
    const int b = bc >> 6, c = bc & 63;
    const int t0  = c * CH;
    const int d2b = (quad & 1) * 128;
    const int d1b = (quad >> 1) * 128;

    const int tid  = threadIdx.x;
    const int wid  = tid >> 5;
    const int lane = tid & 31;
    const int gId  = lane >> 2;
    const int tig  = lane & 3;
    const int wm0 = (wid & 3) * 32;    // d2
    const int wn0 = (wid >> 2) * 64;   // d1

    {
        const int j = tid >> 2, part = tid & 3;
        const size_t gr = ((size_t)(b * SEQ + t0 + j)) * DIMN;
        const __nv_bfloat16* pvh = g_vhi + gr + d2b + part * 32;
        const __nv_bfloat16* pvl = g_vlo + gr + d2b + part * 32;
        const __nv_bfloat16* pkh = g_kdhi + gr + d1b + part * 32;
        const __nv_bfloat16* pkl = g_kdlo + gr + d1b + part * 32;
        __nv_bfloat16* dvh = sVhi + j * VSTR + part * 32;
        __nv_bfloat16* dvl = sVlo + j * VSTR + part * 32;
        __nv_bfloat16* dkh = sKhi + j * VSTR + part * 32;
        __nv_bfloat16* dkl = sKlo + j * VSTR + part * 32;
#pragma unroll
        for (int u = 0; u < 4; u++) {
            *(uint4*)(dvh + u * 8) = *(const uint4*)(pvh + u * 8);
            *(uint4*)(dvl + u * 8) = *(const uint4*)(pvl + u * 8);
            *(uint4*)(dkh + u * 8) = *(const uint4*)(pkh + u * 8);
            *(uint4*)(dkl + u * 8) = *(const uint4*)(pkl + u * 8);
        }
    }
    __syncthreads();

    const uint32_t svhi = (uint32_t)__cvta_generic_to_shared(sVhi);
    const uint32_t svlo = (uint32_t)__cvta_generic_to_shared(sVlo);
    const uint32_t skhi = (uint32_t)__cvta_generic_to_shared(sKhi);
    const uint32_t sklo = (uint32_t)__cvta_generic_to_shared(sKlo);

    const int l8 = lane & 7;
    const int arow = ((lane >> 4) & 1) * 8 + l8;
    const int acol = ((lane >> 3) & 1) * 8;
    const int brow = ((lane >> 3) & 1) * 8 + l8;
    const int bcol = ((lane >> 4) & 1) * 8;

    float acc[2][8][4];
#pragma unroll
    for (int i = 0; i < 2; i++)
#pragma unroll
        for (int j = 0; j < 8; j++)
#pragma unroll
            for (int r = 0; r < 4; r++) acc[i][j][r] = 0.0f;

#pragma unroll
    for (int kk = 0; kk < 4; kk++) {
        const int j0 = kk * 16;
        uint32_t ah[2][4], al[2][4];
#pragma unroll
        for (int it = 0; it < 2; it++) {
            const int d2c = wm0 + it * 16;
            const uint32_t off = (uint32_t)(((j0 + arow) * VSTR + d2c + acol) * 2);
            ldsm4t(ah[it], svhi + off);
            ldsm4t(al[it], svlo + off);
        }
#pragma unroll
        for (int jp = 0; jp < 4; jp++) {
            const int d1c = wn0 + jp * 16;
            const uint32_t boff = (uint32_t)(((j0 + brow) * VSTR + d1c + bcol) * 2);
            uint32_t bh[4], bl[4];
            ldsm4t(bh, skhi + boff);
            ldsm4t(bl, sklo + boff);
            mma16816(acc[0][jp * 2],     ah[0], bh);
            mma16816(acc[0][jp * 2],     ah[0], bl);
            mma16816(acc[0][jp * 2],     al[0], bh);
            mma16816(acc[1][jp * 2],     ah[1], bh);
            mma16816(acc[1][jp * 2],     ah[1], bl);
            mma16816(acc[1][jp * 2],     al[1], bh);
            mma16816(acc[0][jp * 2 + 1], ah[0], bh + 2);
            mma16816(acc[0][jp * 2 + 1], ah[0], bl + 2);
            mma16816(acc[0][jp * 2 + 1], al[0], bh + 2);
            mma16816(acc[1][jp * 2 + 1], ah[1], bh + 2);
            mma16816(acc[1][jp * 2 + 1], ah[1], bl + 2);
            mma16816(acc[1][jp * 2 + 1], al[1], bh + 2);
        }
    }

    const size_t obase = ((size_t)(b * NC + c)) * DIMN * DIMN;
#pragma unroll
    for (int it = 0; it < 2; it++) {
        const int r0 = d2b + wm0 + it * 16 + gId;
#pragma unroll
        for (int jn = 0; jn < 8; jn++) {
            const int col = d1b + wn0 + jn * 8 + tig * 2;
            *(float2*)(g_dAT + obase + (size_t)r0 * DIMN + col)
                = make_float2(acc[it][jn][0], acc[it][jn][1]);
            *(float2*)(g_dAT + obase + (size_t)(r0 + 8) * DIMN + col)
                = make_float2(acc[it][jn][2], acc[it][jn][3]);
        }
    }
}

// ---------------- state combine (transposed): AsT prefix, bf16 split -------
__global__ __launch_bounds__(256) void state_combine_kernel(
    const float* __restrict__ st_in, float* __restrict__ st_out)
{
    const int idx = blockIdx.x * 256 + threadIdx.x;
    const int b = idx >> 16;
    const int e = idx & 65535;
    const int te = ((e & 255) << 8) | (e >> 8);
    float A = st_in[(size_t)b * 65536 + te];
    const float lc = 0.00117901845f;   // 0.9^64
    const size_t base = ((size_t)b * NC) * 65536 + e;
#pragma unroll 4
    for (int c = 0; c < NC; c++) {
        __nv_bfloat16 h = __float2bfloat16(A);
        g_AsThi[base + (size_t)c * 65536] = h;
        g_AsTlo[base + (size_t)c * 65536] = __float2bfloat16(A - __bfloat162float(h));
        A = lc * A + g_dAT[base + (size_t)c * 65536];
    }
    if (st_out) st_out[(size_t)b * 65536 + te] = A;
}

// ---------------- y_inter via HMMA: y = y_intra + lam^(i+1) Q @ A_prev -----
#define YI_SMEM ((2*64 + 2*256) * ASTR * 2)   // 92160 bytes

__global__ __launch_bounds__(256, 2) void y_inter_hmma_kernel()
{
    extern __shared__ __align__(16) __nv_bfloat16 smem[];
    __nv_bfloat16* sQhi = smem;
    __nv_bfloat16* sQlo = smem + 64 * ASTR;
    __nv_bfloat16* sBhi = smem + 2 * 64 * ASTR;
    __nv_bfloat16* sBlo = smem + 2 * 64 * ASTR + 256 * ASTR;

    const int b  = blockIdx.x >> 6;
    const int c  = blockIdx.x & 63;
    const int t0 = c * CH;

    const int tid  = threadIdx.x;
    const int wid  = tid >> 5;
    const int lane = tid & 31;
    const int gId  = lane >> 2;
    const int tig  = lane & 3;
    const int wm0 = (wid & 1) * 32;
    const int wn0 = (wid >> 1) * 64;

    const size_t Abase = ((size_t)(b * NC + c)) * 65536;

    float acc[2][8][4];
#pragma unroll
    for (int i = 0; i < 2; i++)
#pragma unroll
        for (int j = 0; j < 8; j++)
#pragma unroll
            for (int r = 0; r < 4; r++) acc[i][j][r] = 0.0f;

    for (int kc = 0; kc < 4; kc++) {
        __syncthreads();
        {
            const int row = tid >> 2;
            const int seg = tid & 3;
            const size_t gq = ((size_t)(b * SEQ + t0 + row)) * DIMN + kc * 64 + seg * 16;
#pragma unroll
            for (int u = 0; u < 2; u++) {
                *(uint4*)(sQhi + row * ASTR + seg * 16 + u * 8)
                    = *(const uint4*)(g_qhi + gq + u * 8);
                *(uint4*)(sQlo + row * ASTR + seg * 16 + u * 8)
                    = *(const uint4*)(g_qlo + gq + u * 8);
            }
        }
        {
            const int u = tid & 7;
            const int rbase = tid >> 3;
#pragma unroll
            for (int w = 0; w < 8; w++) {
                const int row = w * 32 + rbase;
                const size_t gofs = Abase + (size_t)row * DIMN + kc * 64 + u * 8;
                *(uint4*)(sBhi + row * ASTR + u * 8) = *(const uint4*)(g_AsThi + gofs);
                *(uint4*)(sBlo + row * ASTR + u * 8) = *(const uint4*)(g_AsTlo + gofs);
            }
        }
        __syncthreads();

#pragma unroll
        for (int kk = 0; kk < 4; kk++) {
            const int k0 = kk * 16 + tig * 2;
            uint32_t ah[2][4], al[2][4];
#pragma unroll
            for (int i = 0; i < 2; i++) {
                const int r0 = wm0 + i * 16 + gId;
                ah[i][0] = *(const uint32_t*)(sQhi + r0 * ASTR + k0);
                ah[i][1] = *(const uint32_t*)(sQhi + (r0 + 8) * ASTR + k0);
                ah[i][2] = *(const uint32_t*)(sQhi + r0 * ASTR + k0 + 8);
                ah[i][3] = *(const uint32_t*)(sQhi + (r0 + 8) * ASTR + k0 + 8);
                al[i][0] = *(const uint32_t*)(sQlo + r0 * ASTR + k0);
                al[i][1] = *(const uint32_t*)(sQlo + (r0 + 8) * ASTR + k0);
                al[i][2] = *(const uint32_t*)(sQlo + r0 * ASTR + k0 + 8);
                al[i][3] = *(const uint32_t*)(sQlo + (r0 + 8) * ASTR + k0 + 8);
            }
#pragma unroll
            for (int j = 0; j < 8; j++) {
                const int nr = wn0 + j * 8 + gId;
                uint32_t bh[2], bl[2];
                bh[0] = *(const uint32_t*)(sBhi + nr * ASTR + k0);
                bh[1] = *(const uint32_t*)(sBhi + nr * ASTR + k0 + 8);
                bl[0] = *(const uint32_t*)(sBlo + nr * ASTR + k0);
                bl[1] = *(const uint32_t*)(sBlo + nr * ASTR + k0 + 8);
                mma16816(acc[0][j], ah[0], bh);
                mma16816(acc[0][j], ah[0], bl);
                mma16816(acc[0][j], al[0], bh);
                mma16816(acc[1][j], ah[1], bh);
                mma16816(acc[1][j], ah[1], bl);
                mma16816(acc[1][j], al[1], bh);
            }
        }
    }

    const size_t ybase = ((size_t)(b * SEQ + t0)) * DIMN;
#pragma unroll
    for (int i = 0; i < 2; i++) {
        const int r0 = wm0 + i * 16 + gId;
        const float s0 = powf(DECAYC, (float)(r0 + 1));
        const float s1 = powf(DECAYC, (float)(r0 + 9));
#pragma unroll
        for (int j = 0; j < 8; j++) {
            const int col = wn0 + j * 8 + tig * 2;
            const size_t e0 = ybase + (size_t)r0 * DIMN + col;
            const size_t e1 = ybase + (size_t)(r0 + 8) * DIMN + col;
            float2 o0 = *(float2*)(g_y + e0);
            float2 o1 = *(float2*)(g_y + e1);
            o0.x += s0 * acc[i][j][0]; o0.y += s0 * acc[i][j][1];
            o1.x += s1 * acc[i][j][2]; o1.y += s1 * acc[i][j][3];
            split_store(g_yhi, g_ylo, e0, o0.x, o0.y);
            split_store(g_yhi, g_ylo, e1, o1.x, o1.y);
        }
    }
}

// ---------------- launch ---------------------------------------------------
extern "C" void kernel_launch(void* const* d_in, const int* in_sizes, int n_in,
                              void* d_out, int out_size)
{
    const float* x  = (const float*)d_in[0];
    const float* st = (const float*)d_in[1];
    const float* Wk = (const float*)d_in[2];
    const float* bk = (const float*)d_in[3];
    const float* Wv = (const float*)d_in[4];
    const float* bv = (const float*)d_in[5];
    const float* Wq = (const float*)d_in[6];
    const float* bq = (const float*)d_in[7];
    const float* Wo = (const float*)d_in[8];
    const float* bo = (const float*)d_in[9];

    float* out = (float*)d_out;
    float* state_out = nullptr;
    const long long need = (long long)BATCH * SEQ * DIMN + (long long)BATCH * DIMN * DIMN;
    if ((long long)out_size >= need)
        state_out = out + (size_t)BATCH * SEQ * DIMN;

    void *p;
    cudaGetSymbolAddress(&p, g_v);    float* pv = (float*)p;
    cudaGetSymbolAddress(&p, g_yhi);  __nv_bfloat16* pyh = (__nv_bfloat16*)p;
    cudaGetSymbolAddress(&p, g_ylo);  __nv_bfloat16* pyl = (__nv_bfloat16*)p;
    cudaGetSymbolAddress(&p, g_qhi);  __nv_bfloat16* pqh = (__nv_bfloat16*)p;
    cudaGetSymbolAddress(&p, g_qlo);  __nv_bfloat16* pql = (__nv_bfloat16*)p;
    cudaGetSymbolAddress(&p, g_khi);  __nv_bfloat16* pkh = (__nv_bfloat16*)p;
    cudaGetSymbolAddress(&p, g_klo);  __nv_bfloat16* pkl = (__nv_bfloat16*)p;
    cudaGetSymbolAddress(&p, g_kdhi); __nv_bfloat16* pkdh = (__nv_bfloat16*)p;
    cudaGetSymbolAddress(&p, g_kdlo); __nv_bfloat16* pkdl = (__nv_bfloat16*)p;
    cudaGetSymbolAddress(&p, g_vhi);  __nv_bfloat16* pvh = (__nv_bfloat16*)p;
    cudaGetSymbolAddress(&p, g_vlo);  __nv_bfloat16* pvl = (__nv_bfloat16*)p;
    cudaGetSymbolAddress(&p, g_whi);  __nv_bfloat16* pwh = (__nv_bfloat16*)p;
    cudaGetSymbolAddress(&p, g_wlo);  __nv_bfloat16* pwl = (__nv_bfloat16*)p;

    cudaFuncSetAttribute(hmma_gemm_kernel,
                         cudaFuncAttributeMaxDynamicSharedMemorySize, HG_SMEM);
    cudaFuncSetAttribute(attn_local_kernel,
                         cudaFuncAttributeMaxDynamicSharedMemorySize, AL_SMEM);
    cudaFuncSetAttribute(dAT_hmma_kernel,
                         cudaFuncAttributeMaxDynamicSharedMemorySize, DAT_SMEM);
    cudaFuncSetAttribute(y_inter_hmma_kernel,
                         cudaFuncAttributeMaxDynamicSharedMemorySize, YI_SMEM);

    const int WSZ = DIMN * DIMN;          // 65536

    // fused weight split: Wk,Wv,Wq,Wo -> g_whi/g_wlo[4*WSZ] in ONE launch
    conv_split_w4_kernel<<<256, 256>>>(Wk, Wv, Wq, Wo, pwh, pwl);

    // fused k/v/q projections (A = x fp32, split in-register), one launch z=3
    {
        GemmJobs jobs;
        jobs.j[0] = { pwh + 0 * WSZ, pwl + 0 * WSZ, bk, nullptr,
                      pkh, pkl, pkdh, pkdl, LRC };
        jobs.j[1] = { pwh + 1 * WSZ, pwl + 1 * WSZ, bv, pv,
                      pvh, pvl, nullptr, nullptr, 1.0f };
        jobs.j[2] = { pwh + 2 * WSZ, pwl + 2 * WSZ, bq, nullptr,
                      pqh, pql, nullptr, nullptr, 1.0f };
        dim3 g(MTOT / 128, 2, 3);
        hmma_gemm_kernel<<<g, 256, HG_SMEM>>>(x, nullptr, nullptr, jobs);
    }

    // chunked scan path
    attn_local_kernel<<<BATCH * NC, 256, AL_SMEM>>>();          // Y_intra -> g_y
    dAT_hmma_kernel<<<BATCH * NC * 4, 256, DAT_SMEM>>>();       // dA^T per chunk
    state_combine_kernel<<<2048, 256>>>(st, state_out);         // prefix -> AsT bf16
    y_inter_hmma_kernel<<<BATCH * NC, 256, YI_SMEM>>>();        // final y split

    // output projection (A = y pre-split)
    {
        GemmJobs jobs;
        jobs.j[0] = { pwh + 3 * WSZ, pwl + 3 * WSZ, bo, out,
                      nullptr, nullptr, nullptr, nullptr, 1.0f };
        jobs.j[1] = jobs.j[0];
        jobs.j[2] = jobs.j[0];
        dim3 g(MTOT / 128, 2, 1);
        hmma_gemm_kernel<<<g, 256, HG_SMEM>>>(nullptr, pyh, pyl, jobs);
    }
}